// round 9
// baseline (speedup 1.0000x reference)
#include <cuda_runtime.h>
#include <cstdint>

// Problem constants: B=8, T=1024, F=512, H=8, D=64, P=2047
__device__ float g_qu[8 * 8 * 1024 * 64];   // [B,H,T,D] (q + pos_bias_u) * scale
__device__ float g_qv[8 * 8 * 1024 * 64];   // [B,H,T,D] (q + pos_bias_v) * scale
__device__ float g_k [8 * 8 * 1024 * 64];   // [B,H,T,D]
__device__ float g_v [8 * 8 * 1024 * 64];   // [B,H,T,D]
__device__ float g_p [8 * 2047 * 64];       // [H,P,D]
__device__ float g_att[8 * 1024 * 512];     // [B*T, F]

__device__ __forceinline__ void mma8(float c[4], const uint32_t a[4],
                                     uint32_t b0, uint32_t b1) {
    asm volatile(
        "mma.sync.aligned.m16n8k8.row.col.f32.tf32.tf32.f32 "
        "{%0,%1,%2,%3},{%4,%5,%6,%7},{%8,%9},{%0,%1,%2,%3};"
        : "+f"(c[0]), "+f"(c[1]), "+f"(c[2]), "+f"(c[3])
        : "r"(a[0]), "r"(a[1]), "r"(a[2]), "r"(a[3]), "r"(b0), "r"(b1));
}

// Round-half-up into tf32: +2^12 on the raw bits, hw mma truncates 13 bits.
// Unbiased (vs plain truncation which is biased toward zero).
__device__ __forceinline__ uint4 rnd4(uint4 v) {
    v.x += 0x1000u; v.y += 0x1000u; v.z += 0x1000u; v.w += 0x1000u;
    return v;
}

// ---------------------------------------------------------------------------
// TF32 NT GEMM core: C[m,n] = sum_k A[m,k]*W[n,k]. N=K=512.
// Block tile 128x64, BK=32, register-prefetch double buffering.
// Rounded fp32 bits fed to tf32 mma; STS.128 staging.
// 256 threads = 8 warps (4m x 2n), warp tile 32x32.
// ---------------------------------------------------------------------------
#define AST 36

__device__ __forceinline__ void gemm_core(
    const float* __restrict__ A, const float* __restrict__ W, int M,
    int m0, int n0, uint32_t* As, uint32_t* Ws, float acc[2][4][4])
{
    const int tid = threadIdx.x;
    const int warp = tid >> 5, lane = tid & 31;
    const int gid = lane >> 2, tig = lane & 3;
    const int wm = warp & 3, wn = warp >> 2;

#pragma unroll
    for (int mt = 0; mt < 2; mt++)
#pragma unroll
        for (int nt = 0; nt < 4; nt++)
#pragma unroll
            for (int i = 0; i < 4; i++) acc[mt][nt][i] = 0.f;

    uint4 pa[4], pw[2];
    const uint4 z4 = make_uint4(0u, 0u, 0u, 0u);

    // Prefetch k0 = 0 (rounded at load)
#pragma unroll
    for (int r = 0; r < 4; r++) {
        int ch = tid + r * 256;
        int row = ch >> 3, c4 = (ch & 7) << 2;
        int gm = m0 + row;
        pa[r] = (gm < M) ? rnd4(*(const uint4*)(A + (size_t)gm * 512 + c4)) : z4;
    }
#pragma unroll
    for (int r = 0; r < 2; r++) {
        int ch = tid + r * 256;
        int row = ch >> 3, c4 = (ch & 7) << 2;
        pw[r] = rnd4(*(const uint4*)(W + (size_t)(n0 + row) * 512 + c4));
    }

    for (int it = 0; it < 16; it++) {
        // Commit prefetched tile to smem (one STS.128 each)
#pragma unroll
        for (int r = 0; r < 4; r++) {
            int ch = tid + r * 256;
            int row = ch >> 3, c4 = (ch & 7) << 2;
            *(uint4*)&As[row * AST + c4] = pa[r];
        }
#pragma unroll
        for (int r = 0; r < 2; r++) {
            int ch = tid + r * 256;
            int row = ch >> 3, c4 = (ch & 7) << 2;
            *(uint4*)&Ws[row * AST + c4] = pw[r];
        }
        __syncthreads();

        // Prefetch next tile into registers (latency overlapped with mma)
        if (it + 1 < 16) {
            int k0 = (it + 1) * 32;
#pragma unroll
            for (int r = 0; r < 4; r++) {
                int ch = tid + r * 256;
                int row = ch >> 3, c4 = (ch & 7) << 2;
                int gm = m0 + row;
                pa[r] = (gm < M)
                    ? rnd4(*(const uint4*)(A + (size_t)gm * 512 + k0 + c4)) : z4;
            }
#pragma unroll
            for (int r = 0; r < 2; r++) {
                int ch = tid + r * 256;
                int row = ch >> 3, c4 = (ch & 7) << 2;
                pw[r] = rnd4(*(const uint4*)(W + (size_t)(n0 + row) * 512 + k0 + c4));
            }
        }

        // Compute current tile from smem
#pragma unroll
        for (int ks = 0; ks < 4; ks++) {
            uint32_t a[2][4];
#pragma unroll
            for (int mt = 0; mt < 2; mt++) {
                int rb = wm * 32 + mt * 16 + gid, cb = ks * 8 + tig;
                a[mt][0] = As[rb * AST + cb];
                a[mt][1] = As[(rb + 8) * AST + cb];
                a[mt][2] = As[rb * AST + cb + 4];
                a[mt][3] = As[(rb + 8) * AST + cb + 4];
            }
#pragma unroll
            for (int nt = 0; nt < 4; nt++) {
                int nb = wn * 32 + nt * 8 + gid;
                uint32_t b0 = Ws[nb * AST + ks * 8 + tig];
                uint32_t b1 = Ws[nb * AST + ks * 8 + tig + 4];
                mma8(acc[0][nt], a[0], b0, b1);
                mma8(acc[1][nt], a[1], b0, b1);
            }
        }
        __syncthreads();
    }
}

// Fused Q/K/V/P projection GEMM. blockIdx.z selects operand set.
__global__ __launch_bounds__(256) void gemm_fused(
    const float* __restrict__ query, const float* __restrict__ key,
    const float* __restrict__ value, const float* __restrict__ pos,
    const float* __restrict__ Wq, const float* __restrict__ Wk,
    const float* __restrict__ Wv, const float* __restrict__ Wp,
    const float* __restrict__ bq, const float* __restrict__ bk,
    const float* __restrict__ bvb, const float* __restrict__ bu,
    const float* __restrict__ bvv,
    float* __restrict__ o_qu, float* __restrict__ o_qv,
    float* __restrict__ o_k, float* __restrict__ o_v,
    float* __restrict__ o_p)
{
    __shared__ __align__(16) uint32_t As[128 * AST];
    __shared__ __align__(16) uint32_t Ws[64 * AST];

    const int z = blockIdx.z;
    const float *A, *W;
    int M;
    if (z == 0)      { A = query; W = Wq; M = 8192; }
    else if (z == 1) { A = key;   W = Wk; M = 8192; }
    else if (z == 2) { A = value; W = Wv; M = 8192; }
    else             { A = pos;   W = Wp; M = 2047; }

    const int m0 = blockIdx.y * 128, n0 = blockIdx.x * 64;
    if (m0 >= M) return;

    float acc[2][4][4];
    gemm_core(A, W, M, m0, n0, As, Ws, acc);

    const int tid = threadIdx.x;
    const int warp = tid >> 5, lane = tid & 31;
    const int gid = lane >> 2, tig = lane & 3;
    const int wm = warp & 3, wn = warp >> 2;
    const float scale = 0.125f;

#pragma unroll
    for (int mt = 0; mt < 2; mt++) {
#pragma unroll
        for (int hh = 0; hh < 2; hh++) {
            int m = m0 + wm * 32 + mt * 16 + gid + 8 * hh;
            if (m >= M) continue;
#pragma unroll
            for (int nt = 0; nt < 4; nt++) {
#pragma unroll
                for (int cc = 0; cc < 2; cc++) {
                    int n = n0 + wn * 32 + nt * 8 + 2 * tig + cc;
                    float v = acc[mt][nt][2 * hh + cc];
                    if (z == 0) {
                        int b = m >> 10, t = m & 1023, h = n >> 6, d = n & 63;
                        size_t idx = (((size_t)(b * 8 + h) << 10) + t) * 64 + d;
                        float base = v + bq[n];
                        o_qu[idx] = (base + bu[n]) * scale;
                        o_qv[idx] = (base + bvv[n]) * scale;
                    } else if (z == 1) {
                        int b = m >> 10, t = m & 1023, h = n >> 6, d = n & 63;
                        o_k[(((size_t)(b * 8 + h) << 10) + t) * 64 + d] =
                            v + bk[n];
                    } else if (z == 2) {
                        int b = m >> 10, t = m & 1023, h = n >> 6, d = n & 63;
                        o_v[(((size_t)(b * 8 + h) << 10) + t) * 64 + d] =
                            v + bvb[n];
                    } else {
                        int h = n >> 6, d = n & 63;
                        o_p[((size_t)h * 2047 + m) * 64 + d] = v;
                    }
                }
            }
        }
    }
}

// Output projection GEMM: d_out = att @ Wo^T + bo.
__global__ __launch_bounds__(256) void gemm_out(
    const float* __restrict__ A, const float* __restrict__ W,
    const float* __restrict__ bias, float* __restrict__ out)
{
    __shared__ __align__(16) uint32_t As[128 * AST];
    __shared__ __align__(16) uint32_t Ws[64 * AST];

    const int m0 = blockIdx.y * 128, n0 = blockIdx.x * 64;
    float acc[2][4][4];
    gemm_core(A, W, 8192, m0, n0, As, Ws, acc);

    const int tid = threadIdx.x;
    const int warp = tid >> 5, lane = tid & 31;
    const int gid = lane >> 2, tig = lane & 3;
    const int wm = warp & 3, wn = warp >> 2;

#pragma unroll
    for (int mt = 0; mt < 2; mt++)
#pragma unroll
        for (int hh = 0; hh < 2; hh++) {
            int m = m0 + wm * 32 + mt * 16 + gid + 8 * hh;
#pragma unroll
            for (int nt = 0; nt < 4; nt++)
#pragma unroll
                for (int cc = 0; cc < 2; cc++) {
                    int n = n0 + wn * 32 + nt * 8 + 2 * tig + cc;
                    out[(size_t)m * 512 + n] = acc[mt][nt][2 * hh + cc] + bias[n];
                }
        }
}

// ---------------------------------------------------------------------------
// Tensor-core flash attention with relative positions.
// scores[i,j] = qu[i]·k[j] + comp[i][j], comp[i][j] = (Qv·P_slab^T)[i][63+j-i]
// 256 threads = 8 warps: warp w = (row group wr=w>>1 [16 rows], j/d half
// wc=w&1 [32 cols]). Pairs reduce softmax stats via named barriers.
// Rounded fp32 bits to tf32 mma; STS.128 staging; 88KB smem -> 2 CTAs/SM.
// ---------------------------------------------------------------------------
#define QST 68
#define ATT_SMEM_U32 (2 * 64 * QST + 128 * QST + 64 * QST + 256)
#define ATT_SMEM_BYTES (ATT_SMEM_U32 * 4)

__global__ __launch_bounds__(256) void attn_mma(
    const float* __restrict__ qu, const float* __restrict__ qv,
    const float* __restrict__ kk, const float* __restrict__ vv,
    const float* __restrict__ pp, float* __restrict__ att)
{
    extern __shared__ __align__(16) uint32_t sh[];
    uint32_t* Ks = sh;                       // Qu staging, then K / exp(S)
    uint32_t* Vs = sh + 64 * QST;            // Qv staging, then V
    uint32_t* Ps = sh + 2 * 64 * QST;        // 128-row P slab
    float*    Cp = (float*)(sh + 2 * 64 * QST + 128 * QST);  // 64x68 band
    float*    Rmax = (float*)(sh + 2 * 64 * QST + 128 * QST + 64 * QST); // [2][64]
    float*    Rsum = Rmax + 128;                                          // [2][64]

    const int tid = threadIdx.x;
    const int w = tid >> 5, lane = tid & 31;
    const int gid = lane >> 2, tig = lane & 3;
    const int wr = w >> 1, wc = w & 1;       // row group / col half
    const int i0 = blockIdx.x << 6;
    const int bh = blockIdx.y;
    const int h = bh & 7, b = bh >> 3;

    // Stage Q tiles (rounded bits) into K/V buffers, extract frags, release.
#pragma unroll
    for (int r = 0; r < 4; r++) {
        int fi = tid + r * 256;
        int row = fi >> 4, c4 = (fi & 15) << 2;
        size_t g = ((size_t)bh * 1024 + i0 + row) * 64 + c4;
        *(uint4*)&Ks[row * QST + c4] = rnd4(*(const uint4*)(qu + g));
        *(uint4*)&Vs[row * QST + c4] = rnd4(*(const uint4*)(qv + g));
    }
    __syncthreads();

    uint32_t qua[8][4], qva[8][4];
#pragma unroll
    for (int ks = 0; ks < 8; ks++) {
        int rb = wr * 16 + gid, cb = ks * 8 + tig;
        qua[ks][0] = Ks[rb * QST + cb];
        qua[ks][1] = Ks[(rb + 8) * QST + cb];
        qua[ks][2] = Ks[rb * QST + cb + 4];
        qua[ks][3] = Ks[(rb + 8) * QST + cb + 4];
        qva[ks][0] = Vs[rb * QST + cb];
        qva[ks][1] = Vs[(rb + 8) * QST + cb];
        qva[ks][2] = Vs[rb * QST + cb + 4];
        qva[ks][3] = Vs[(rb + 8) * QST + cb + 4];
    }

    float m_i[2] = {-1e30f, -1e30f}, l_i[2] = {0.f, 0.f};
    float oC[4][4];
#pragma unroll
    for (int nt = 0; nt < 4; nt++)
#pragma unroll
        for (int i = 0; i < 4; i++) oC[nt][i] = 0.f;

    // E band window for row group wr: cols [48-16wr, 126-16wr]
    const int lo = 48 - wr * 16, hi = 126 - wr * 16;

    for (int jt = 0; jt < 16; jt++) {
        const int j0 = jt << 6;
        __syncthreads();   // prior iteration (and Q staging) done with smem

        // Stage K, V tiles (rounded bits, STS.128)
#pragma unroll
        for (int r = 0; r < 4; r++) {
            int fi = tid + r * 256;
            int row = fi >> 4, c4 = (fi & 15) << 2;
            size_t g = ((size_t)bh * 1024 + j0 + row) * 64 + c4;
            *(uint4*)&Ks[row * QST + c4] = rnd4(*(const uint4*)(kk + g));
            *(uint4*)&Vs[row * QST + c4] = rnd4(*(const uint4*)(vv + g));
        }
        // Stage P slab rows rbase..rbase+127 (row 127 pads an unused E col)
        const int rbase = 960 + j0 - i0;
#pragma unroll
        for (int r = 0; r < 8; r++) {
            int fi = tid + r * 256;
            int row = fi >> 4, c4 = (fi & 15) << 2;
            int prow = rbase + row;
            prow = prow > 2046 ? 2046 : prow;
            *(uint4*)&Ps[row * QST + c4] =
                rnd4(*(const uint4*)(pp + ((size_t)h * 2047 + prow) * 64 + c4));
        }
        __syncthreads();

        // E = Qv @ P_slab^T over band n-tiles of this warp's parity half.
#pragma unroll
        for (int nt = 0; nt < 16; nt++) {
            if (nt * 8 + 7 < lo || nt * 8 > hi) continue;
            if ((nt & 1) != wc) continue;
            float e[4] = {0.f, 0.f, 0.f, 0.f};
#pragma unroll
            for (int ks = 0; ks < 8; ks++) {
                int rb = nt * 8 + gid, cb = ks * 8 + tig;
                mma8(e, qva[ks], Ps[rb * QST + cb], Ps[rb * QST + cb + 4]);
            }
            int er = wr * 16 + gid, ec = nt * 8 + 2 * tig;
#pragma unroll
            for (int hh = 0; hh < 2; hh++) {
#pragma unroll
                for (int cc = 0; cc < 2; cc++) {
                    int row = er + 8 * hh;
                    int col = ec + cc - 63 + row;   // j index
                    if (col >= 0 && col < 64)
                        Cp[row * QST + col] = e[2 * hh + cc];
                }
            }
        }

        // S1 = Qu @ K^T, this warp's j-half (4 n-tiles)
        float sC[4][4];
#pragma unroll
        for (int nt = 0; nt < 4; nt++)
#pragma unroll
            for (int i = 0; i < 4; i++) sC[nt][i] = 0.f;
#pragma unroll
        for (int ks = 0; ks < 8; ks++) {
#pragma unroll
            for (int nt = 0; nt < 4; nt++) {
                int nb = (wc * 4 + nt) * 8 + gid;
                mma8(sC[nt], qua[ks],
                     Ks[nb * QST + ks * 8 + tig],
                     Ks[nb * QST + ks * 8 + tig + 4]);
            }
        }
        __syncthreads();   // all warps done reading Ks; Cp writes visible

        // Softmax phase A: partial max per row over this warp's 16 cols
        float sv[2][8], pmx[2];
#pragma unroll
        for (int hh = 0; hh < 2; hh++) {
            int qrow = wr * 16 + gid + 8 * hh;
            float mx = -1e30f;
#pragma unroll
            for (int nt = 0; nt < 4; nt++) {
#pragma unroll
                for (int cc = 0; cc < 2; cc++) {
                    int jl = (wc * 4 + nt) * 8 + 2 * tig + cc;
                    float s = sC[nt][2 * hh + cc] + Cp[qrow * QST + jl];
                    sv[hh][nt * 2 + cc] = s;
                    mx = fmaxf(mx, s);
                }
            }
            mx = fmaxf(mx, __shfl_xor_sync(0xffffffffu, mx, 1));
            mx = fmaxf(mx, __shfl_xor_sync(0xffffffffu, mx, 2));
            pmx[hh] = mx;
            Rmax[wc * 64 + qrow] = mx;
        }
        asm volatile("bar.sync %0, %1;" :: "r"(wr + 1), "r"(64) : "memory");

        // Phase B: combine max across pair, exp, partial sums, exp->Ks
        float al[2];
#pragma unroll
        for (int hh = 0; hh < 2; hh++) {
            int qrow = wr * 16 + gid + 8 * hh;
            float mo = fmaxf(Rmax[qrow], Rmax[64 + qrow]);
            float mn = fmaxf(m_i[hh], mo);
            al[hh] = __expf(m_i[hh] - mn);
            m_i[hh] = mn;
            float rs = 0.f;
#pragma unroll
            for (int t = 0; t < 8; t++) {
                float p = __expf(sv[hh][t] - mn);
                rs += p;
                int nt = t >> 1, cc = t & 1;
                int jl = (wc * 4 + nt) * 8 + 2 * tig + cc;
                Ks[qrow * QST + jl] = __float_as_uint(p) + 0x1000u;
            }
            rs += __shfl_xor_sync(0xffffffffu, rs, 1);
            rs += __shfl_xor_sync(0xffffffffu, rs, 2);
            Rsum[wc * 64 + qrow] = rs;
#pragma unroll
            for (int nt = 0; nt < 4; nt++) {
                oC[nt][2 * hh] *= al[hh];
                oC[nt][2 * hh + 1] *= al[hh];
            }
        }
        asm volatile("bar.sync %0, %1;" :: "r"(wr + 1), "r"(64) : "memory");

#pragma unroll
        for (int hh = 0; hh < 2; hh++) {
            int qrow = wr * 16 + gid + 8 * hh;
            l_i[hh] = l_i[hh] * al[hh] + Rsum[qrow] + Rsum[64 + qrow];
        }

        // O += exp(S) @ V (this warp's d-half)
#pragma unroll
        for (int ks = 0; ks < 8; ks++) {
            uint32_t a[4];
            int rb = wr * 16 + gid, cb = ks * 8 + tig;
            a[0] = Ks[rb * QST + cb];
            a[1] = Ks[(rb + 8) * QST + cb];
            a[2] = Ks[rb * QST + cb + 4];
            a[3] = Ks[(rb + 8) * QST + cb + 4];
#pragma unroll
            for (int nt = 0; nt < 4; nt++) {
                int nb = (wc * 4 + nt) * 8 + gid;
                uint32_t b0 = Vs[(ks * 8 + tig) * QST + nb];
                uint32_t b1 = Vs[(ks * 8 + tig + 4) * QST + nb];
                mma8(oC[nt], a, b0, b1);
            }
        }
    }

    // Write normalized output: att[b, t, h*64+d]
#pragma unroll
    for (int hh = 0; hh < 2; hh++) {
        int t = i0 + wr * 16 + gid + 8 * hh;
        float inv = 1.f / l_i[hh];
#pragma unroll
        for (int nt = 0; nt < 4; nt++) {
            int d = wc * 32 + nt * 8 + 2 * tig;
            size_t o = (((size_t)b * 1024 + t) * 8 + h) * 64 + d;
            att[o]     = oC[nt][2 * hh] * inv;
            att[o + 1] = oC[nt][2 * hh + 1] * inv;
        }
    }
}

// ---------------------------------------------------------------------------
extern "C" void kernel_launch(void* const* d_in, const int* in_sizes, int n_in,
                              void* d_out, int out_size)
{
    const float* query = (const float*)d_in[0];
    const float* key   = (const float*)d_in[1];
    const float* value = (const float*)d_in[2];
    const float* pos   = (const float*)d_in[3];
    const float* Wq    = (const float*)d_in[4];
    const float* bq    = (const float*)d_in[5];
    const float* Wk    = (const float*)d_in[6];
    const float* bk    = (const float*)d_in[7];
    const float* Wv    = (const float*)d_in[8];
    const float* bv_   = (const float*)d_in[9];
    const float* Wp    = (const float*)d_in[10];
    const float* Wo    = (const float*)d_in[11];
    const float* bo    = (const float*)d_in[12];
    const float* pbu   = (const float*)d_in[13];
    const float* pbv   = (const float*)d_in[14];

    float *qu_p, *qv_p, *k_p, *v_p, *p_p, *att_p;
    cudaGetSymbolAddress((void**)&qu_p,  g_qu);
    cudaGetSymbolAddress((void**)&qv_p,  g_qv);
    cudaGetSymbolAddress((void**)&k_p,   g_k);
    cudaGetSymbolAddress((void**)&v_p,   g_v);
    cudaGetSymbolAddress((void**)&p_p,   g_p);
    cudaGetSymbolAddress((void**)&att_p, g_att);

    cudaFuncSetAttribute(attn_mma,
                         cudaFuncAttributeMaxDynamicSharedMemorySize,
                         ATT_SMEM_BYTES);

    gemm_fused<<<dim3(8, 64, 4), 256>>>(
        query, key, value, pos, Wq, Wk, Wv, Wp,
        bq, bk, bv_, pbu, pbv,
        qu_p, qv_p, k_p, v_p, p_p);

    attn_mma<<<dim3(16, 64), dim3(256), ATT_SMEM_BYTES>>>(qu_p, qv_p, k_p, v_p,
                                                          p_p, att_p);

    gemm_out<<<dim3(8, 64), 256>>>(att_p, Wo, bo, (float*)d_out);
}

// round 10
// speedup vs baseline: 1.0035x; 1.0035x over previous
#include <cuda_runtime.h>
#include <cstdint>

// Problem constants: B=8, T=1024, F=512, H=8, D=64, P=2047
__device__ float g_qu[8 * 8 * 1024 * 64];   // [B,H,T,D] (q + pos_bias_u) * scale
__device__ float g_qv[8 * 8 * 1024 * 64];   // [B,H,T,D] (q + pos_bias_v) * scale
__device__ float g_k [8 * 8 * 1024 * 64];   // [B,H,T,D]
__device__ float g_v [8 * 8 * 1024 * 64];   // [B,H,T,D]
__device__ float g_p [8 * 2047 * 64];       // [H,P,D]
__device__ float g_att[8 * 1024 * 512];     // [B*T, F]

__device__ __forceinline__ void mma8(float c[4], const uint32_t a[4],
                                     uint32_t b0, uint32_t b1) {
    asm volatile(
        "mma.sync.aligned.m16n8k8.row.col.f32.tf32.tf32.f32 "
        "{%0,%1,%2,%3},{%4,%5,%6,%7},{%8,%9},{%0,%1,%2,%3};"
        : "+f"(c[0]), "+f"(c[1]), "+f"(c[2]), "+f"(c[3])
        : "r"(a[0]), "r"(a[1]), "r"(a[2]), "r"(a[3]), "r"(b0), "r"(b1));
}

// Round-half-up into tf32: +2^12 on the raw bits, hw mma truncates 13 bits.
// Unbiased (vs plain truncation which is biased toward zero).
__device__ __forceinline__ uint4 rnd4(uint4 v) {
    v.x += 0x1000u; v.y += 0x1000u; v.z += 0x1000u; v.w += 0x1000u;
    return v;
}

// ---------------------------------------------------------------------------
// TF32 NT GEMM core: C[m,n] = sum_k A[m,k]*W[n,k]. N=K=512.
// Block tile 128x64, BK=32, register-prefetch double buffering.
// Rounded fp32 bits fed to tf32 mma; STS.128 staging.
// 256 threads = 8 warps (4m x 2n), warp tile 32x32.
// ---------------------------------------------------------------------------
#define AST 36

__device__ __forceinline__ void gemm_core(
    const float* __restrict__ A, const float* __restrict__ W, int M,
    int m0, int n0, uint32_t* As, uint32_t* Ws, float acc[2][4][4])
{
    const int tid = threadIdx.x;
    const int warp = tid >> 5, lane = tid & 31;
    const int gid = lane >> 2, tig = lane & 3;
    const int wm = warp & 3, wn = warp >> 2;

#pragma unroll
    for (int mt = 0; mt < 2; mt++)
#pragma unroll
        for (int nt = 0; nt < 4; nt++)
#pragma unroll
            for (int i = 0; i < 4; i++) acc[mt][nt][i] = 0.f;

    uint4 pa[4], pw[2];
    const uint4 z4 = make_uint4(0u, 0u, 0u, 0u);

    // Prefetch k0 = 0 (rounded at load)
#pragma unroll
    for (int r = 0; r < 4; r++) {
        int ch = tid + r * 256;
        int row = ch >> 3, c4 = (ch & 7) << 2;
        int gm = m0 + row;
        pa[r] = (gm < M) ? rnd4(*(const uint4*)(A + (size_t)gm * 512 + c4)) : z4;
    }
#pragma unroll
    for (int r = 0; r < 2; r++) {
        int ch = tid + r * 256;
        int row = ch >> 3, c4 = (ch & 7) << 2;
        pw[r] = rnd4(*(const uint4*)(W + (size_t)(n0 + row) * 512 + c4));
    }

    for (int it = 0; it < 16; it++) {
        // Commit prefetched tile to smem (one STS.128 each)
#pragma unroll
        for (int r = 0; r < 4; r++) {
            int ch = tid + r * 256;
            int row = ch >> 3, c4 = (ch & 7) << 2;
            *(uint4*)&As[row * AST + c4] = pa[r];
        }
#pragma unroll
        for (int r = 0; r < 2; r++) {
            int ch = tid + r * 256;
            int row = ch >> 3, c4 = (ch & 7) << 2;
            *(uint4*)&Ws[row * AST + c4] = pw[r];
        }
        __syncthreads();

        // Prefetch next tile into registers (latency overlapped with mma)
        if (it + 1 < 16) {
            int k0 = (it + 1) * 32;
#pragma unroll
            for (int r = 0; r < 4; r++) {
                int ch = tid + r * 256;
                int row = ch >> 3, c4 = (ch & 7) << 2;
                int gm = m0 + row;
                pa[r] = (gm < M)
                    ? rnd4(*(const uint4*)(A + (size_t)gm * 512 + k0 + c4)) : z4;
            }
#pragma unroll
            for (int r = 0; r < 2; r++) {
                int ch = tid + r * 256;
                int row = ch >> 3, c4 = (ch & 7) << 2;
                pw[r] = rnd4(*(const uint4*)(W + (size_t)(n0 + row) * 512 + k0 + c4));
            }
        }

        // Compute current tile from smem
#pragma unroll
        for (int ks = 0; ks < 4; ks++) {
            uint32_t a[2][4];
#pragma unroll
            for (int mt = 0; mt < 2; mt++) {
                int rb = wm * 32 + mt * 16 + gid, cb = ks * 8 + tig;
                a[mt][0] = As[rb * AST + cb];
                a[mt][1] = As[(rb + 8) * AST + cb];
                a[mt][2] = As[rb * AST + cb + 4];
                a[mt][3] = As[(rb + 8) * AST + cb + 4];
            }
#pragma unroll
            for (int nt = 0; nt < 4; nt++) {
                int nb = wn * 32 + nt * 8 + gid;
                uint32_t b0 = Ws[nb * AST + ks * 8 + tig];
                uint32_t b1 = Ws[nb * AST + ks * 8 + tig + 4];
                mma8(acc[0][nt], a[0], b0, b1);
                mma8(acc[1][nt], a[1], b0, b1);
            }
        }
        __syncthreads();
    }
}

// Fused Q/K/V/P projection GEMM. blockIdx.z selects operand set.
__global__ __launch_bounds__(256) void gemm_fused(
    const float* __restrict__ query, const float* __restrict__ key,
    const float* __restrict__ value, const float* __restrict__ pos,
    const float* __restrict__ Wq, const float* __restrict__ Wk,
    const float* __restrict__ Wv, const float* __restrict__ Wp,
    const float* __restrict__ bq, const float* __restrict__ bk,
    const float* __restrict__ bvb, const float* __restrict__ bu,
    const float* __restrict__ bvv,
    float* __restrict__ o_qu, float* __restrict__ o_qv,
    float* __restrict__ o_k, float* __restrict__ o_v,
    float* __restrict__ o_p)
{
    __shared__ __align__(16) uint32_t As[128 * AST];
    __shared__ __align__(16) uint32_t Ws[64 * AST];

    const int z = blockIdx.z;
    const float *A, *W;
    int M;
    if (z == 0)      { A = query; W = Wq; M = 8192; }
    else if (z == 1) { A = key;   W = Wk; M = 8192; }
    else if (z == 2) { A = value; W = Wv; M = 8192; }
    else             { A = pos;   W = Wp; M = 2047; }

    const int m0 = blockIdx.y * 128, n0 = blockIdx.x * 64;
    if (m0 >= M) return;

    float acc[2][4][4];
    gemm_core(A, W, M, m0, n0, As, Ws, acc);

    const int tid = threadIdx.x;
    const int warp = tid >> 5, lane = tid & 31;
    const int gid = lane >> 2, tig = lane & 3;
    const int wm = warp & 3, wn = warp >> 2;
    const float scale = 0.125f;

#pragma unroll
    for (int mt = 0; mt < 2; mt++) {
#pragma unroll
        for (int hh = 0; hh < 2; hh++) {
            int m = m0 + wm * 32 + mt * 16 + gid + 8 * hh;
            if (m >= M) continue;
#pragma unroll
            for (int nt = 0; nt < 4; nt++) {
#pragma unroll
                for (int cc = 0; cc < 2; cc++) {
                    int n = n0 + wn * 32 + nt * 8 + 2 * tig + cc;
                    float v = acc[mt][nt][2 * hh + cc];
                    if (z == 0) {
                        int b = m >> 10, t = m & 1023, h = n >> 6, d = n & 63;
                        size_t idx = (((size_t)(b * 8 + h) << 10) + t) * 64 + d;
                        float base = v + bq[n];
                        o_qu[idx] = (base + bu[n]) * scale;
                        o_qv[idx] = (base + bvv[n]) * scale;
                    } else if (z == 1) {
                        int b = m >> 10, t = m & 1023, h = n >> 6, d = n & 63;
                        o_k[(((size_t)(b * 8 + h) << 10) + t) * 64 + d] =
                            v + bk[n];
                    } else if (z == 2) {
                        int b = m >> 10, t = m & 1023, h = n >> 6, d = n & 63;
                        o_v[(((size_t)(b * 8 + h) << 10) + t) * 64 + d] =
                            v + bvb[n];
                    } else {
                        int h = n >> 6, d = n & 63;
                        o_p[((size_t)h * 2047 + m) * 64 + d] = v;
                    }
                }
            }
        }
    }
}

// Output projection GEMM: d_out = att @ Wo^T + bo.
__global__ __launch_bounds__(256) void gemm_out(
    const float* __restrict__ A, const float* __restrict__ W,
    const float* __restrict__ bias, float* __restrict__ out)
{
    __shared__ __align__(16) uint32_t As[128 * AST];
    __shared__ __align__(16) uint32_t Ws[64 * AST];

    const int m0 = blockIdx.y * 128, n0 = blockIdx.x * 64;
    float acc[2][4][4];
    gemm_core(A, W, 8192, m0, n0, As, Ws, acc);

    const int tid = threadIdx.x;
    const int warp = tid >> 5, lane = tid & 31;
    const int gid = lane >> 2, tig = lane & 3;
    const int wm = warp & 3, wn = warp >> 2;

#pragma unroll
    for (int mt = 0; mt < 2; mt++)
#pragma unroll
        for (int hh = 0; hh < 2; hh++) {
            int m = m0 + wm * 32 + mt * 16 + gid + 8 * hh;
#pragma unroll
            for (int nt = 0; nt < 4; nt++)
#pragma unroll
                for (int cc = 0; cc < 2; cc++) {
                    int n = n0 + wn * 32 + nt * 8 + 2 * tig + cc;
                    out[(size_t)m * 512 + n] = acc[mt][nt][2 * hh + cc] + bias[n];
                }
        }
}

// ---------------------------------------------------------------------------
// Tensor-core flash attention with relative positions.
// scores[i,j] = qu[i]·k[j] + comp[i][j], comp[i][j] = (Qv·P_slab^T)[i][63+j-i]
// 256 threads = 8 warps: warp w = (row group wr=w>>1 [16 rows], j/d half
// wc=w&1 [32 cols]). Pairs reduce softmax stats via named barriers.
// Rounded fp32 bits to tf32 mma; STS.128 staging; 88KB smem -> 2 CTAs/SM.
// ---------------------------------------------------------------------------
#define QST 68
#define ATT_SMEM_U32 (2 * 64 * QST + 128 * QST + 64 * QST + 256)
#define ATT_SMEM_BYTES (ATT_SMEM_U32 * 4)

__global__ __launch_bounds__(256) void attn_mma(
    const float* __restrict__ qu, const float* __restrict__ qv,
    const float* __restrict__ kk, const float* __restrict__ vv,
    const float* __restrict__ pp, float* __restrict__ att)
{
    extern __shared__ __align__(16) uint32_t sh[];
    uint32_t* Ks = sh;                       // Qu staging, then K / exp(S)
    uint32_t* Vs = sh + 64 * QST;            // Qv staging, then V
    uint32_t* Ps = sh + 2 * 64 * QST;        // 128-row P slab
    float*    Cp = (float*)(sh + 2 * 64 * QST + 128 * QST);  // 64x68 band
    float*    Rmax = (float*)(sh + 2 * 64 * QST + 128 * QST + 64 * QST); // [2][64]
    float*    Rsum = Rmax + 128;                                          // [2][64]

    const int tid = threadIdx.x;
    const int w = tid >> 5, lane = tid & 31;
    const int gid = lane >> 2, tig = lane & 3;
    const int wr = w >> 1, wc = w & 1;       // row group / col half
    const int i0 = blockIdx.x << 6;
    const int bh = blockIdx.y;
    const int h = bh & 7, b = bh >> 3;

    // Stage Q tiles (rounded bits) into K/V buffers, extract frags, release.
#pragma unroll
    for (int r = 0; r < 4; r++) {
        int fi = tid + r * 256;
        int row = fi >> 4, c4 = (fi & 15) << 2;
        size_t g = ((size_t)bh * 1024 + i0 + row) * 64 + c4;
        *(uint4*)&Ks[row * QST + c4] = rnd4(*(const uint4*)(qu + g));
        *(uint4*)&Vs[row * QST + c4] = rnd4(*(const uint4*)(qv + g));
    }
    __syncthreads();

    uint32_t qua[8][4], qva[8][4];
#pragma unroll
    for (int ks = 0; ks < 8; ks++) {
        int rb = wr * 16 + gid, cb = ks * 8 + tig;
        qua[ks][0] = Ks[rb * QST + cb];
        qua[ks][1] = Ks[(rb + 8) * QST + cb];
        qua[ks][2] = Ks[rb * QST + cb + 4];
        qua[ks][3] = Ks[(rb + 8) * QST + cb + 4];
        qva[ks][0] = Vs[rb * QST + cb];
        qva[ks][1] = Vs[(rb + 8) * QST + cb];
        qva[ks][2] = Vs[rb * QST + cb + 4];
        qva[ks][3] = Vs[(rb + 8) * QST + cb + 4];
    }

    float m_i[2] = {-1e30f, -1e30f}, l_i[2] = {0.f, 0.f};
    float oC[4][4];
#pragma unroll
    for (int nt = 0; nt < 4; nt++)
#pragma unroll
        for (int i = 0; i < 4; i++) oC[nt][i] = 0.f;

    // E band window for row group wr: cols [48-16wr, 126-16wr]
    const int lo = 48 - wr * 16, hi = 126 - wr * 16;

    for (int jt = 0; jt < 16; jt++) {
        const int j0 = jt << 6;
        __syncthreads();   // prior iteration (and Q staging) done with smem

        // Stage K, V tiles (rounded bits, STS.128)
#pragma unroll
        for (int r = 0; r < 4; r++) {
            int fi = tid + r * 256;
            int row = fi >> 4, c4 = (fi & 15) << 2;
            size_t g = ((size_t)bh * 1024 + j0 + row) * 64 + c4;
            *(uint4*)&Ks[row * QST + c4] = rnd4(*(const uint4*)(kk + g));
            *(uint4*)&Vs[row * QST + c4] = rnd4(*(const uint4*)(vv + g));
        }
        // Stage P slab rows rbase..rbase+127 (row 127 pads an unused E col)
        const int rbase = 960 + j0 - i0;
#pragma unroll
        for (int r = 0; r < 8; r++) {
            int fi = tid + r * 256;
            int row = fi >> 4, c4 = (fi & 15) << 2;
            int prow = rbase + row;
            prow = prow > 2046 ? 2046 : prow;
            *(uint4*)&Ps[row * QST + c4] =
                rnd4(*(const uint4*)(pp + ((size_t)h * 2047 + prow) * 64 + c4));
        }
        __syncthreads();

        // E = Qv @ P_slab^T over band n-tiles of this warp's parity half.
#pragma unroll
        for (int nt = 0; nt < 16; nt++) {
            if (nt * 8 + 7 < lo || nt * 8 > hi) continue;
            if ((nt & 1) != wc) continue;
            float e[4] = {0.f, 0.f, 0.f, 0.f};
#pragma unroll
            for (int ks = 0; ks < 8; ks++) {
                int rb = nt * 8 + gid, cb = ks * 8 + tig;
                mma8(e, qva[ks], Ps[rb * QST + cb], Ps[rb * QST + cb + 4]);
            }
            int er = wr * 16 + gid, ec = nt * 8 + 2 * tig;
#pragma unroll
            for (int hh = 0; hh < 2; hh++) {
#pragma unroll
                for (int cc = 0; cc < 2; cc++) {
                    int row = er + 8 * hh;
                    int col = ec + cc - 63 + row;   // j index
                    if (col >= 0 && col < 64)
                        Cp[row * QST + col] = e[2 * hh + cc];
                }
            }
        }

        // S1 = Qu @ K^T, this warp's j-half (4 n-tiles)
        float sC[4][4];
#pragma unroll
        for (int nt = 0; nt < 4; nt++)
#pragma unroll
            for (int i = 0; i < 4; i++) sC[nt][i] = 0.f;
#pragma unroll
        for (int ks = 0; ks < 8; ks++) {
#pragma unroll
            for (int nt = 0; nt < 4; nt++) {
                int nb = (wc * 4 + nt) * 8 + gid;
                mma8(sC[nt], qua[ks],
                     Ks[nb * QST + ks * 8 + tig],
                     Ks[nb * QST + ks * 8 + tig + 4]);
            }
        }
        __syncthreads();   // all warps done reading Ks; Cp writes visible

        // Softmax phase A: partial max per row over this warp's 16 cols
        float sv[2][8], pmx[2];
#pragma unroll
        for (int hh = 0; hh < 2; hh++) {
            int qrow = wr * 16 + gid + 8 * hh;
            float mx = -1e30f;
#pragma unroll
            for (int nt = 0; nt < 4; nt++) {
#pragma unroll
                for (int cc = 0; cc < 2; cc++) {
                    int jl = (wc * 4 + nt) * 8 + 2 * tig + cc;
                    float s = sC[nt][2 * hh + cc] + Cp[qrow * QST + jl];
                    sv[hh][nt * 2 + cc] = s;
                    mx = fmaxf(mx, s);
                }
            }
            mx = fmaxf(mx, __shfl_xor_sync(0xffffffffu, mx, 1));
            mx = fmaxf(mx, __shfl_xor_sync(0xffffffffu, mx, 2));
            pmx[hh] = mx;
            Rmax[wc * 64 + qrow] = mx;
        }
        asm volatile("bar.sync %0, %1;" :: "r"(wr + 1), "r"(64) : "memory");

        // Phase B: combine max across pair, exp, partial sums, exp->Ks
        float al[2];
#pragma unroll
        for (int hh = 0; hh < 2; hh++) {
            int qrow = wr * 16 + gid + 8 * hh;
            float mo = fmaxf(Rmax[qrow], Rmax[64 + qrow]);
            float mn = fmaxf(m_i[hh], mo);
            al[hh] = __expf(m_i[hh] - mn);
            m_i[hh] = mn;
            float rs = 0.f;
#pragma unroll
            for (int t = 0; t < 8; t++) {
                float p = __expf(sv[hh][t] - mn);
                rs += p;
                int nt = t >> 1, cc = t & 1;
                int jl = (wc * 4 + nt) * 8 + 2 * tig + cc;
                Ks[qrow * QST + jl] = __float_as_uint(p) + 0x1000u;
            }
            rs += __shfl_xor_sync(0xffffffffu, rs, 1);
            rs += __shfl_xor_sync(0xffffffffu, rs, 2);
            Rsum[wc * 64 + qrow] = rs;
#pragma unroll
            for (int nt = 0; nt < 4; nt++) {
                oC[nt][2 * hh] *= al[hh];
                oC[nt][2 * hh + 1] *= al[hh];
            }
        }
        asm volatile("bar.sync %0, %1;" :: "r"(wr + 1), "r"(64) : "memory");

#pragma unroll
        for (int hh = 0; hh < 2; hh++) {
            int qrow = wr * 16 + gid + 8 * hh;
            l_i[hh] = l_i[hh] * al[hh] + Rsum[qrow] + Rsum[64 + qrow];
        }

        // O += exp(S) @ V (this warp's d-half)
#pragma unroll
        for (int ks = 0; ks < 8; ks++) {
            uint32_t a[4];
            int rb = wr * 16 + gid, cb = ks * 8 + tig;
            a[0] = Ks[rb * QST + cb];
            a[1] = Ks[(rb + 8) * QST + cb];
            a[2] = Ks[rb * QST + cb + 4];
            a[3] = Ks[(rb + 8) * QST + cb + 4];
#pragma unroll
            for (int nt = 0; nt < 4; nt++) {
                int nb = (wc * 4 + nt) * 8 + gid;
                uint32_t b0 = Vs[(ks * 8 + tig) * QST + nb];
                uint32_t b1 = Vs[(ks * 8 + tig + 4) * QST + nb];
                mma8(oC[nt], a, b0, b1);
            }
        }
    }

    // Write normalized output: att[b, t, h*64+d]
#pragma unroll
    for (int hh = 0; hh < 2; hh++) {
        int t = i0 + wr * 16 + gid + 8 * hh;
        float inv = 1.f / l_i[hh];
#pragma unroll
        for (int nt = 0; nt < 4; nt++) {
            int d = wc * 32 + nt * 8 + 2 * tig;
            size_t o = (((size_t)b * 1024 + t) * 8 + h) * 64 + d;
            att[o]     = oC[nt][2 * hh] * inv;
            att[o + 1] = oC[nt][2 * hh + 1] * inv;
        }
    }
}

// ---------------------------------------------------------------------------
extern "C" void kernel_launch(void* const* d_in, const int* in_sizes, int n_in,
                              void* d_out, int out_size)
{
    const float* query = (const float*)d_in[0];
    const float* key   = (const float*)d_in[1];
    const float* value = (const float*)d_in[2];
    const float* pos   = (const float*)d_in[3];
    const float* Wq    = (const float*)d_in[4];
    const float* bq    = (const float*)d_in[5];
    const float* Wk    = (const float*)d_in[6];
    const float* bk    = (const float*)d_in[7];
    const float* Wv    = (const float*)d_in[8];
    const float* bv_   = (const float*)d_in[9];
    const float* Wp    = (const float*)d_in[10];
    const float* Wo    = (const float*)d_in[11];
    const float* bo    = (const float*)d_in[12];
    const float* pbu   = (const float*)d_in[13];
    const float* pbv   = (const float*)d_in[14];

    float *qu_p, *qv_p, *k_p, *v_p, *p_p, *att_p;
    cudaGetSymbolAddress((void**)&qu_p,  g_qu);
    cudaGetSymbolAddress((void**)&qv_p,  g_qv);
    cudaGetSymbolAddress((void**)&k_p,   g_k);
    cudaGetSymbolAddress((void**)&v_p,   g_v);
    cudaGetSymbolAddress((void**)&p_p,   g_p);
    cudaGetSymbolAddress((void**)&att_p, g_att);

    cudaFuncSetAttribute(attn_mma,
                         cudaFuncAttributeMaxDynamicSharedMemorySize,
                         ATT_SMEM_BYTES);

    gemm_fused<<<dim3(8, 64, 4), 256>>>(
        query, key, value, pos, Wq, Wk, Wv, Wp,
        bq, bk, bv_, pbu, pbv,
        qu_p, qv_p, k_p, v_p, p_p);

    attn_mma<<<dim3(16, 64), dim3(256), ATT_SMEM_BYTES>>>(qu_p, qv_p, k_p, v_p,
                                                          p_p, att_p);

    gemm_out<<<dim3(8, 64), 256>>>(att_p, Wo, bo, (float*)d_out);
}

// round 11
// speedup vs baseline: 1.0596x; 1.0559x over previous
#include <cuda_runtime.h>
#include <cstdint>

// Problem constants: B=8, T=1024, F=512, H=8, D=64, P=2047
__device__ float g_qu[8 * 8 * 1024 * 64];   // [B,H,T,D] (q + pos_bias_u) * scale
__device__ float g_qv[8 * 8 * 1024 * 64];   // [B,H,T,D] (q + pos_bias_v) * scale
__device__ float g_k [8 * 8 * 1024 * 64];   // [B,H,T,D]
__device__ float g_v [8 * 8 * 1024 * 64];   // [B,H,T,D]
__device__ float g_p [8 * 2047 * 64];       // [H,P,D]
__device__ float g_att[8 * 1024 * 512];     // [B*T, F]

__device__ __forceinline__ void mma8(float c[4], const uint32_t a[4],
                                     uint32_t b0, uint32_t b1) {
    asm volatile(
        "mma.sync.aligned.m16n8k8.row.col.f32.tf32.tf32.f32 "
        "{%0,%1,%2,%3},{%4,%5,%6,%7},{%8,%9},{%0,%1,%2,%3};"
        : "+f"(c[0]), "+f"(c[1]), "+f"(c[2]), "+f"(c[3])
        : "r"(a[0]), "r"(a[1]), "r"(a[2]), "r"(a[3]), "r"(b0), "r"(b1));
}

// Round-half-up into tf32: +2^12 on raw bits, hw mma truncates 13 bits.
__device__ __forceinline__ uint4 rnd4(uint4 v) {
    v.x += 0x1000u; v.y += 0x1000u; v.z += 0x1000u; v.w += 0x1000u;
    return v;
}

// ---------------------------------------------------------------------------
// TF32 NT GEMM core: C[m,n] = sum_k A[m,k]*W[n,k]. N=K=512.
// Block tile 128x64, BK=32, register-prefetch double buffering.
// Rounded fp32 bits fed to tf32 mma; STS.128 staging.
// 256 threads = 8 warps (4m x 2n), warp tile 32x32.
// ---------------------------------------------------------------------------
#define AST 36

__device__ __forceinline__ void gemm_core(
    const float* __restrict__ A, const float* __restrict__ W, int M,
    int m0, int n0, uint32_t* As, uint32_t* Ws, float acc[2][4][4])
{
    const int tid = threadIdx.x;
    const int warp = tid >> 5, lane = tid & 31;
    const int gid = lane >> 2, tig = lane & 3;
    const int wm = warp & 3, wn = warp >> 2;

#pragma unroll
    for (int mt = 0; mt < 2; mt++)
#pragma unroll
        for (int nt = 0; nt < 4; nt++)
#pragma unroll
            for (int i = 0; i < 4; i++) acc[mt][nt][i] = 0.f;

    uint4 pa[4], pw[2];
    const uint4 z4 = make_uint4(0u, 0u, 0u, 0u);

#pragma unroll
    for (int r = 0; r < 4; r++) {
        int ch = tid + r * 256;
        int row = ch >> 3, c4 = (ch & 7) << 2;
        int gm = m0 + row;
        pa[r] = (gm < M) ? rnd4(*(const uint4*)(A + (size_t)gm * 512 + c4)) : z4;
    }
#pragma unroll
    for (int r = 0; r < 2; r++) {
        int ch = tid + r * 256;
        int row = ch >> 3, c4 = (ch & 7) << 2;
        pw[r] = rnd4(*(const uint4*)(W + (size_t)(n0 + row) * 512 + c4));
    }

    for (int it = 0; it < 16; it++) {
#pragma unroll
        for (int r = 0; r < 4; r++) {
            int ch = tid + r * 256;
            int row = ch >> 3, c4 = (ch & 7) << 2;
            *(uint4*)&As[row * AST + c4] = pa[r];
        }
#pragma unroll
        for (int r = 0; r < 2; r++) {
            int ch = tid + r * 256;
            int row = ch >> 3, c4 = (ch & 7) << 2;
            *(uint4*)&Ws[row * AST + c4] = pw[r];
        }
        __syncthreads();

        if (it + 1 < 16) {
            int k0 = (it + 1) * 32;
#pragma unroll
            for (int r = 0; r < 4; r++) {
                int ch = tid + r * 256;
                int row = ch >> 3, c4 = (ch & 7) << 2;
                int gm = m0 + row;
                pa[r] = (gm < M)
                    ? rnd4(*(const uint4*)(A + (size_t)gm * 512 + k0 + c4)) : z4;
            }
#pragma unroll
            for (int r = 0; r < 2; r++) {
                int ch = tid + r * 256;
                int row = ch >> 3, c4 = (ch & 7) << 2;
                pw[r] = rnd4(*(const uint4*)(W + (size_t)(n0 + row) * 512 + k0 + c4));
            }
        }

#pragma unroll
        for (int ks = 0; ks < 4; ks++) {
            uint32_t a[2][4];
#pragma unroll
            for (int mt = 0; mt < 2; mt++) {
                int rb = wm * 32 + mt * 16 + gid, cb = ks * 8 + tig;
                a[mt][0] = As[rb * AST + cb];
                a[mt][1] = As[(rb + 8) * AST + cb];
                a[mt][2] = As[rb * AST + cb + 4];
                a[mt][3] = As[(rb + 8) * AST + cb + 4];
            }
#pragma unroll
            for (int nt = 0; nt < 4; nt++) {
                int nb = wn * 32 + nt * 8 + gid;
                uint32_t b0 = Ws[nb * AST + ks * 8 + tig];
                uint32_t b1 = Ws[nb * AST + ks * 8 + tig + 4];
                mma8(acc[0][nt], a[0], b0, b1);
                mma8(acc[1][nt], a[1], b0, b1);
            }
        }
        __syncthreads();
    }
}

// Fused Q/K/V/P projection GEMM. blockIdx.z selects operand set.
__global__ __launch_bounds__(256) void gemm_fused(
    const float* __restrict__ query, const float* __restrict__ key,
    const float* __restrict__ value, const float* __restrict__ pos,
    const float* __restrict__ Wq, const float* __restrict__ Wk,
    const float* __restrict__ Wv, const float* __restrict__ Wp,
    const float* __restrict__ bq, const float* __restrict__ bk,
    const float* __restrict__ bvb, const float* __restrict__ bu,
    const float* __restrict__ bvv,
    float* __restrict__ o_qu, float* __restrict__ o_qv,
    float* __restrict__ o_k, float* __restrict__ o_v,
    float* __restrict__ o_p)
{
    __shared__ __align__(16) uint32_t As[128 * AST];
    __shared__ __align__(16) uint32_t Ws[64 * AST];

    const int z = blockIdx.z;
    const float *A, *W;
    int M;
    if (z == 0)      { A = query; W = Wq; M = 8192; }
    else if (z == 1) { A = key;   W = Wk; M = 8192; }
    else if (z == 2) { A = value; W = Wv; M = 8192; }
    else             { A = pos;   W = Wp; M = 2047; }

    const int m0 = blockIdx.y * 128, n0 = blockIdx.x * 64;
    if (m0 >= M) return;

    float acc[2][4][4];
    gemm_core(A, W, M, m0, n0, As, Ws, acc);

    const int tid = threadIdx.x;
    const int warp = tid >> 5, lane = tid & 31;
    const int gid = lane >> 2, tig = lane & 3;
    const int wm = warp & 3, wn = warp >> 2;
    const float scale = 0.125f;

#pragma unroll
    for (int mt = 0; mt < 2; mt++) {
#pragma unroll
        for (int hh = 0; hh < 2; hh++) {
            int m = m0 + wm * 32 + mt * 16 + gid + 8 * hh;
            if (m >= M) continue;
#pragma unroll
            for (int nt = 0; nt < 4; nt++) {
#pragma unroll
                for (int cc = 0; cc < 2; cc++) {
                    int n = n0 + wn * 32 + nt * 8 + 2 * tig + cc;
                    float v = acc[mt][nt][2 * hh + cc];
                    if (z == 0) {
                        int b = m >> 10, t = m & 1023, h = n >> 6, d = n & 63;
                        size_t idx = (((size_t)(b * 8 + h) << 10) + t) * 64 + d;
                        float base = v + bq[n];
                        o_qu[idx] = (base + bu[n]) * scale;
                        o_qv[idx] = (base + bvv[n]) * scale;
                    } else if (z == 1) {
                        int b = m >> 10, t = m & 1023, h = n >> 6, d = n & 63;
                        o_k[(((size_t)(b * 8 + h) << 10) + t) * 64 + d] =
                            v + bk[n];
                    } else if (z == 2) {
                        int b = m >> 10, t = m & 1023, h = n >> 6, d = n & 63;
                        o_v[(((size_t)(b * 8 + h) << 10) + t) * 64 + d] =
                            v + bvb[n];
                    } else {
                        int h = n >> 6, d = n & 63;
                        o_p[((size_t)h * 2047 + m) * 64 + d] = v;
                    }
                }
            }
        }
    }
}

// Output projection GEMM: d_out = att @ Wo^T + bo.
__global__ __launch_bounds__(256) void gemm_out(
    const float* __restrict__ A, const float* __restrict__ W,
    const float* __restrict__ bias, float* __restrict__ out)
{
    __shared__ __align__(16) uint32_t As[128 * AST];
    __shared__ __align__(16) uint32_t Ws[64 * AST];

    const int m0 = blockIdx.y * 128, n0 = blockIdx.x * 64;
    float acc[2][4][4];
    gemm_core(A, W, 8192, m0, n0, As, Ws, acc);

    const int tid = threadIdx.x;
    const int warp = tid >> 5, lane = tid & 31;
    const int gid = lane >> 2, tig = lane & 3;
    const int wm = warp & 3, wn = warp >> 2;

#pragma unroll
    for (int mt = 0; mt < 2; mt++)
#pragma unroll
        for (int hh = 0; hh < 2; hh++) {
            int m = m0 + wm * 32 + mt * 16 + gid + 8 * hh;
#pragma unroll
            for (int nt = 0; nt < 4; nt++)
#pragma unroll
                for (int cc = 0; cc < 2; cc++) {
                    int n = n0 + wn * 32 + nt * 8 + 2 * tig + cc;
                    out[(size_t)m * 512 + n] = acc[mt][nt][2 * hh + cc] + bias[n];
                }
        }
}

// ---------------------------------------------------------------------------
// Tensor-core flash attention with relative positions, 128 queries per CTA.
// scores[i,j] = qu[i]·k[j] + comp[i][j], comp[i][j] = (Qv·P_slab^T)[i][...]
// 256 threads = 8 warps; warp w owns query rows [16w,16w+16), full j-width
// (proven R8 loop structure). K/V/P staged once per 128 queries. exp(S)
// lives in Cp (warp-private rows) -> Ks never overwritten -> 2 barriers/jt.
// Raw-bit tf32 staging (truncation); K=64 contractions keep the error small.
// ---------------------------------------------------------------------------
#define QST 68
// Ks 64 + Vs 64 + Ps 192 + Cp 128 rows, all stride QST
#define ATT_SMEM_U32 ((64 + 64 + 192 + 128) * QST)
#define ATT_SMEM_BYTES (ATT_SMEM_U32 * 4)

__global__ __launch_bounds__(256) void attn_mma(
    const float* __restrict__ qu, const float* __restrict__ qv,
    const float* __restrict__ kk, const float* __restrict__ vv,
    const float* __restrict__ pp, float* __restrict__ att)
{
    extern __shared__ __align__(16) uint32_t sh[];
    uint32_t* Ks = sh;                        // K tile (64 rows)
    uint32_t* Vs = sh + 64 * QST;             // V tile (64 rows)
    uint32_t* Ps = sh + 2 * 64 * QST;         // P slab (192 rows)
    uint32_t* CpU = sh + (2 * 64 + 192) * QST; // bias band / exp(S), 128 rows
    float*    Cp = (float*)CpU;

    const int tid = threadIdx.x;
    const int w = tid >> 5, lane = tid & 31;
    const int gid = lane >> 2, tig = lane & 3;
    const int i0 = blockIdx.x << 7;           // 128-query tile
    const int bh = blockIdx.y;
    const int h = bh & 7, b = bh >> 3;

    // --- Stage Qu (128x64) into rows 0..127 (Ks+Vs region), extract frags ---
#pragma unroll
    for (int r = 0; r < 8; r++) {
        int fi = tid + r * 256;
        int row = fi >> 4, c4 = (fi & 15) << 2;
        size_t g = ((size_t)bh * 1024 + i0 + row) * 64 + c4;
        *(uint4*)&sh[row * QST + c4] = *(const uint4*)(qu + g);
    }
    __syncthreads();
    uint32_t qua[8][4];
#pragma unroll
    for (int ks = 0; ks < 8; ks++) {
        int rb = w * 16 + gid, cb = ks * 8 + tig;
        qua[ks][0] = sh[rb * QST + cb];
        qua[ks][1] = sh[(rb + 8) * QST + cb];
        qua[ks][2] = sh[rb * QST + cb + 4];
        qua[ks][3] = sh[(rb + 8) * QST + cb + 4];
    }
    __syncthreads();
    // --- Stage Qv, extract frags ---
#pragma unroll
    for (int r = 0; r < 8; r++) {
        int fi = tid + r * 256;
        int row = fi >> 4, c4 = (fi & 15) << 2;
        size_t g = ((size_t)bh * 1024 + i0 + row) * 64 + c4;
        *(uint4*)&sh[row * QST + c4] = *(const uint4*)(qv + g);
    }
    __syncthreads();
    uint32_t qva[8][4];
#pragma unroll
    for (int ks = 0; ks < 8; ks++) {
        int rb = w * 16 + gid, cb = ks * 8 + tig;
        qva[ks][0] = sh[rb * QST + cb];
        qva[ks][1] = sh[(rb + 8) * QST + cb];
        qva[ks][2] = sh[rb * QST + cb + 4];
        qva[ks][3] = sh[(rb + 8) * QST + cb + 4];
    }

    float m_i[2] = {-1e30f, -1e30f}, l_i[2] = {0.f, 0.f};
    float oC[8][4];
#pragma unroll
    for (int nt = 0; nt < 8; nt++)
#pragma unroll
        for (int i = 0; i < 4; i++) oC[nt][i] = 0.f;

    // E band for warp w's rows [16w,16w+16): slab cols [112-16w, 190-16w]
    const int lo = 112 - w * 16, hi = 190 - w * 16;

    for (int jt = 0; jt < 16; jt++) {
        const int j0 = jt << 6;
        __syncthreads();   // prior iteration (and Q staging) done with smem

        // Stage K, V tiles (64 rows each)
#pragma unroll
        for (int r = 0; r < 4; r++) {
            int fi = tid + r * 256;
            int row = fi >> 4, c4 = (fi & 15) << 2;
            size_t g = ((size_t)bh * 1024 + j0 + row) * 64 + c4;
            *(uint4*)&Ks[row * QST + c4] = *(const uint4*)(kk + g);
            *(uint4*)&Vs[row * QST + c4] = *(const uint4*)(vv + g);
        }
        // Stage P slab: 192 rows from rbase (row 191 pads, clamped)
        const int rbase = 896 + j0 - i0;
#pragma unroll
        for (int r = 0; r < 12; r++) {
            int fi = tid + r * 256;
            int row = fi >> 4, c4 = (fi & 15) << 2;
            int prow = rbase + row;
            prow = prow > 2046 ? 2046 : prow;
            *(uint4*)&Ps[row * QST + c4] =
                *(const uint4*)(pp + ((size_t)h * 2047 + prow) * 64 + c4);
        }
        __syncthreads();

        // E = Qv @ P_slab^T over band n-tiles; write compacted into Cp.
#pragma unroll
        for (int nt = 0; nt < 24; nt++) {
            if (nt * 8 + 7 < lo || nt * 8 > hi) continue;
            float e[4] = {0.f, 0.f, 0.f, 0.f};
#pragma unroll
            for (int ks = 0; ks < 8; ks++) {
                int rb = nt * 8 + gid, cb = ks * 8 + tig;
                mma8(e, qva[ks], Ps[rb * QST + cb], Ps[rb * QST + cb + 4]);
            }
            int er = w * 16 + gid, ec = nt * 8 + 2 * tig;
#pragma unroll
            for (int hh = 0; hh < 2; hh++) {
#pragma unroll
                for (int cc = 0; cc < 2; cc++) {
                    int row = er + 8 * hh;
                    int col = ec + cc - 127 + row;   // j index
                    if (col >= 0 && col < 64)
                        Cp[row * QST + col] = e[2 * hh + cc];
                }
            }
        }

        // S1 = Qu @ K^T (full j-width, 8 n-tiles)
        float sC[8][4];
#pragma unroll
        for (int nt = 0; nt < 8; nt++)
#pragma unroll
            for (int i = 0; i < 4; i++) sC[nt][i] = 0.f;
#pragma unroll
        for (int ks = 0; ks < 8; ks++) {
#pragma unroll
            for (int nt = 0; nt < 8; nt++) {
                int rb = nt * 8 + gid, cb = ks * 8 + tig;
                mma8(sC[nt], qua[ks], Ks[rb * QST + cb], Ks[rb * QST + cb + 4]);
            }
        }
        // (no block barrier needed: exp goes to Cp, warp-private rows)

        // Online softmax; write exp(S) into Cp (in-place over the bias band)
#pragma unroll
        for (int hh = 0; hh < 2; hh++) {
            int qrow = w * 16 + gid + 8 * hh;
            float sv[16];
            float mx = -1e30f;
#pragma unroll
            for (int nt = 0; nt < 8; nt++) {
#pragma unroll
                for (int cc = 0; cc < 2; cc++) {
                    int jl = nt * 8 + 2 * tig + cc;
                    float s = sC[nt][2 * hh + cc] + Cp[qrow * QST + jl];
                    sv[nt * 2 + cc] = s;
                    mx = fmaxf(mx, s);
                }
            }
            mx = fmaxf(mx, __shfl_xor_sync(0xffffffffu, mx, 1));
            mx = fmaxf(mx, __shfl_xor_sync(0xffffffffu, mx, 2));
            float mn = fmaxf(m_i[hh], mx);
            float al = __expf(m_i[hh] - mn);
            float rs = 0.f;
#pragma unroll
            for (int t = 0; t < 16; t++) {
                float p = __expf(sv[t] - mn);
                rs += p;
                int nt = t >> 1, cc = t & 1;
                int jl = nt * 8 + 2 * tig + cc;
                Cp[qrow * QST + jl] = p;
            }
            rs += __shfl_xor_sync(0xffffffffu, rs, 1);
            rs += __shfl_xor_sync(0xffffffffu, rs, 2);
            l_i[hh] = l_i[hh] * al + rs;
            m_i[hh] = mn;
#pragma unroll
            for (int nt = 0; nt < 8; nt++) {
                oC[nt][2 * hh] *= al;
                oC[nt][2 * hh + 1] *= al;
            }
        }
        __syncwarp();   // exp rows are warp-local

        // O += exp(S) @ V
#pragma unroll
        for (int ks = 0; ks < 8; ks++) {
            uint32_t a[4];
            int rb = w * 16 + gid, cb = ks * 8 + tig;
            a[0] = CpU[rb * QST + cb];
            a[1] = CpU[(rb + 8) * QST + cb];
            a[2] = CpU[rb * QST + cb + 4];
            a[3] = CpU[(rb + 8) * QST + cb + 4];
#pragma unroll
            for (int nt = 0; nt < 8; nt++) {
                uint32_t b0 = Vs[(ks * 8 + tig) * QST + nt * 8 + gid];
                uint32_t b1 = Vs[(ks * 8 + tig + 4) * QST + nt * 8 + gid];
                mma8(oC[nt], a, b0, b1);
            }
        }
    }

    // Write normalized output: att[b, t, h*64+d]
#pragma unroll
    for (int hh = 0; hh < 2; hh++) {
        int t = i0 + w * 16 + gid + 8 * hh;
        float inv = 1.f / l_i[hh];
#pragma unroll
        for (int nt = 0; nt < 8; nt++) {
            int d = nt * 8 + 2 * tig;
            size_t o = (((size_t)b * 1024 + t) * 8 + h) * 64 + d;
            att[o]     = oC[nt][2 * hh] * inv;
            att[o + 1] = oC[nt][2 * hh + 1] * inv;
        }
    }
}

// ---------------------------------------------------------------------------
extern "C" void kernel_launch(void* const* d_in, const int* in_sizes, int n_in,
                              void* d_out, int out_size)
{
    const float* query = (const float*)d_in[0];
    const float* key   = (const float*)d_in[1];
    const float* value = (const float*)d_in[2];
    const float* pos   = (const float*)d_in[3];
    const float* Wq    = (const float*)d_in[4];
    const float* bq    = (const float*)d_in[5];
    const float* Wk    = (const float*)d_in[6];
    const float* bk    = (const float*)d_in[7];
    const float* Wv    = (const float*)d_in[8];
    const float* bv_   = (const float*)d_in[9];
    const float* Wp    = (const float*)d_in[10];
    const float* Wo    = (const float*)d_in[11];
    const float* bo    = (const float*)d_in[12];
    const float* pbu   = (const float*)d_in[13];
    const float* pbv   = (const float*)d_in[14];

    float *qu_p, *qv_p, *k_p, *v_p, *p_p, *att_p;
    cudaGetSymbolAddress((void**)&qu_p,  g_qu);
    cudaGetSymbolAddress((void**)&qv_p,  g_qv);
    cudaGetSymbolAddress((void**)&k_p,   g_k);
    cudaGetSymbolAddress((void**)&v_p,   g_v);
    cudaGetSymbolAddress((void**)&p_p,   g_p);
    cudaGetSymbolAddress((void**)&att_p, g_att);

    cudaFuncSetAttribute(attn_mma,
                         cudaFuncAttributeMaxDynamicSharedMemorySize,
                         ATT_SMEM_BYTES);

    gemm_fused<<<dim3(8, 64, 4), 256>>>(
        query, key, value, pos, Wq, Wk, Wv, Wp,
        bq, bk, bv_, pbu, pbv,
        qu_p, qv_p, k_p, v_p, p_p);

    attn_mma<<<dim3(8, 64), dim3(256), ATT_SMEM_BYTES>>>(qu_p, qv_p, k_p, v_p,
                                                         p_p, att_p);

    gemm_out<<<dim3(8, 64), 256>>>(att_p, Wo, bo, (float*)d_out);
}

// round 12
// speedup vs baseline: 1.1882x; 1.1213x over previous
#include <cuda_runtime.h>
#include <cstdint>

// Problem constants: B=8, T=1024, F=512, H=8, D=64, P=2047
__device__ float g_qu[8 * 8 * 1024 * 64];   // [B,H,T,D] (q + pos_bias_u) * scale
__device__ float g_qv[8 * 8 * 1024 * 64];   // [B,H,T,D] (q + pos_bias_v) * scale
__device__ float g_k [8 * 8 * 1024 * 64];   // [B,H,T,D]
__device__ float g_v [8 * 8 * 1024 * 64];   // [B,H,T,D]
__device__ float g_p [8 * 2047 * 64];       // [H,P,D]
__device__ float g_att[8 * 1024 * 512];     // [B*T, F]

__device__ __forceinline__ void mma8(float c[4], const uint32_t a[4],
                                     uint32_t b0, uint32_t b1) {
    asm volatile(
        "mma.sync.aligned.m16n8k8.row.col.f32.tf32.tf32.f32 "
        "{%0,%1,%2,%3},{%4,%5,%6,%7},{%8,%9},{%0,%1,%2,%3};"
        : "+f"(c[0]), "+f"(c[1]), "+f"(c[2]), "+f"(c[3])
        : "r"(a[0]), "r"(a[1]), "r"(a[2]), "r"(a[3]), "r"(b0), "r"(b1));
}

// Round-half-up into tf32: +2^12 on raw bits, hw mma truncates 13 bits.
__device__ __forceinline__ uint4 rnd4(uint4 v) {
    v.x += 0x1000u; v.y += 0x1000u; v.z += 0x1000u; v.w += 0x1000u;
    return v;
}

// ---------------------------------------------------------------------------
// TF32 NT GEMM core: C[m,n] = sum_k A[m,k]*W[n,k]. N=K=512.
// Block tile 128x64, BK=32, register-prefetch double buffering.
// Rounded fp32 bits fed to tf32 mma; STS.128 staging.
// 256 threads = 8 warps (4m x 2n), warp tile 32x32.
// ---------------------------------------------------------------------------
#define AST 36

__device__ __forceinline__ void gemm_core(
    const float* __restrict__ A, const float* __restrict__ W, int M,
    int m0, int n0, uint32_t* As, uint32_t* Ws, float acc[2][4][4])
{
    const int tid = threadIdx.x;
    const int warp = tid >> 5, lane = tid & 31;
    const int gid = lane >> 2, tig = lane & 3;
    const int wm = warp & 3, wn = warp >> 2;

#pragma unroll
    for (int mt = 0; mt < 2; mt++)
#pragma unroll
        for (int nt = 0; nt < 4; nt++)
#pragma unroll
            for (int i = 0; i < 4; i++) acc[mt][nt][i] = 0.f;

    uint4 pa[4], pw[2];
    const uint4 z4 = make_uint4(0u, 0u, 0u, 0u);

#pragma unroll
    for (int r = 0; r < 4; r++) {
        int ch = tid + r * 256;
        int row = ch >> 3, c4 = (ch & 7) << 2;
        int gm = m0 + row;
        pa[r] = (gm < M) ? rnd4(*(const uint4*)(A + (size_t)gm * 512 + c4)) : z4;
    }
#pragma unroll
    for (int r = 0; r < 2; r++) {
        int ch = tid + r * 256;
        int row = ch >> 3, c4 = (ch & 7) << 2;
        pw[r] = rnd4(*(const uint4*)(W + (size_t)(n0 + row) * 512 + c4));
    }

    for (int it = 0; it < 16; it++) {
#pragma unroll
        for (int r = 0; r < 4; r++) {
            int ch = tid + r * 256;
            int row = ch >> 3, c4 = (ch & 7) << 2;
            *(uint4*)&As[row * AST + c4] = pa[r];
        }
#pragma unroll
        for (int r = 0; r < 2; r++) {
            int ch = tid + r * 256;
            int row = ch >> 3, c4 = (ch & 7) << 2;
            *(uint4*)&Ws[row * AST + c4] = pw[r];
        }
        __syncthreads();

        if (it + 1 < 16) {
            int k0 = (it + 1) * 32;
#pragma unroll
            for (int r = 0; r < 4; r++) {
                int ch = tid + r * 256;
                int row = ch >> 3, c4 = (ch & 7) << 2;
                int gm = m0 + row;
                pa[r] = (gm < M)
                    ? rnd4(*(const uint4*)(A + (size_t)gm * 512 + k0 + c4)) : z4;
            }
#pragma unroll
            for (int r = 0; r < 2; r++) {
                int ch = tid + r * 256;
                int row = ch >> 3, c4 = (ch & 7) << 2;
                pw[r] = rnd4(*(const uint4*)(W + (size_t)(n0 + row) * 512 + k0 + c4));
            }
        }

#pragma unroll
        for (int ks = 0; ks < 4; ks++) {
            uint32_t a[2][4];
#pragma unroll
            for (int mt = 0; mt < 2; mt++) {
                int rb = wm * 32 + mt * 16 + gid, cb = ks * 8 + tig;
                a[mt][0] = As[rb * AST + cb];
                a[mt][1] = As[(rb + 8) * AST + cb];
                a[mt][2] = As[rb * AST + cb + 4];
                a[mt][3] = As[(rb + 8) * AST + cb + 4];
            }
#pragma unroll
            for (int nt = 0; nt < 4; nt++) {
                int nb = wn * 32 + nt * 8 + gid;
                uint32_t b0 = Ws[nb * AST + ks * 8 + tig];
                uint32_t b1 = Ws[nb * AST + ks * 8 + tig + 4];
                mma8(acc[0][nt], a[0], b0, b1);
                mma8(acc[1][nt], a[1], b0, b1);
            }
        }
        __syncthreads();
    }
}

// Fused Q/K/V/P projection GEMM. blockIdx.z selects operand set.
__global__ __launch_bounds__(256) void gemm_fused(
    const float* __restrict__ query, const float* __restrict__ key,
    const float* __restrict__ value, const float* __restrict__ pos,
    const float* __restrict__ Wq, const float* __restrict__ Wk,
    const float* __restrict__ Wv, const float* __restrict__ Wp,
    const float* __restrict__ bq, const float* __restrict__ bk,
    const float* __restrict__ bvb, const float* __restrict__ bu,
    const float* __restrict__ bvv,
    float* __restrict__ o_qu, float* __restrict__ o_qv,
    float* __restrict__ o_k, float* __restrict__ o_v,
    float* __restrict__ o_p)
{
    __shared__ __align__(16) uint32_t As[128 * AST];
    __shared__ __align__(16) uint32_t Ws[64 * AST];

    const int z = blockIdx.z;
    const float *A, *W;
    int M;
    if (z == 0)      { A = query; W = Wq; M = 8192; }
    else if (z == 1) { A = key;   W = Wk; M = 8192; }
    else if (z == 2) { A = value; W = Wv; M = 8192; }
    else             { A = pos;   W = Wp; M = 2047; }

    const int m0 = blockIdx.y * 128, n0 = blockIdx.x * 64;
    if (m0 >= M) return;

    float acc[2][4][4];
    gemm_core(A, W, M, m0, n0, As, Ws, acc);

    const int tid = threadIdx.x;
    const int warp = tid >> 5, lane = tid & 31;
    const int gid = lane >> 2, tig = lane & 3;
    const int wm = warp & 3, wn = warp >> 2;
    const float scale = 0.125f;

#pragma unroll
    for (int mt = 0; mt < 2; mt++) {
#pragma unroll
        for (int hh = 0; hh < 2; hh++) {
            int m = m0 + wm * 32 + mt * 16 + gid + 8 * hh;
            if (m >= M) continue;
#pragma unroll
            for (int nt = 0; nt < 4; nt++) {
#pragma unroll
                for (int cc = 0; cc < 2; cc++) {
                    int n = n0 + wn * 32 + nt * 8 + 2 * tig + cc;
                    float v = acc[mt][nt][2 * hh + cc];
                    if (z == 0) {
                        int b = m >> 10, t = m & 1023, h = n >> 6, d = n & 63;
                        size_t idx = (((size_t)(b * 8 + h) << 10) + t) * 64 + d;
                        float base = v + bq[n];
                        o_qu[idx] = (base + bu[n]) * scale;
                        o_qv[idx] = (base + bvv[n]) * scale;
                    } else if (z == 1) {
                        int b = m >> 10, t = m & 1023, h = n >> 6, d = n & 63;
                        o_k[(((size_t)(b * 8 + h) << 10) + t) * 64 + d] =
                            v + bk[n];
                    } else if (z == 2) {
                        int b = m >> 10, t = m & 1023, h = n >> 6, d = n & 63;
                        o_v[(((size_t)(b * 8 + h) << 10) + t) * 64 + d] =
                            v + bvb[n];
                    } else {
                        int h = n >> 6, d = n & 63;
                        o_p[((size_t)h * 2047 + m) * 64 + d] = v;
                    }
                }
            }
        }
    }
}

// Output projection GEMM: d_out = att @ Wo^T + bo.
__global__ __launch_bounds__(256) void gemm_out(
    const float* __restrict__ A, const float* __restrict__ W,
    const float* __restrict__ bias, float* __restrict__ out)
{
    __shared__ __align__(16) uint32_t As[128 * AST];
    __shared__ __align__(16) uint32_t Ws[64 * AST];

    const int m0 = blockIdx.y * 128, n0 = blockIdx.x * 64;
    float acc[2][4][4];
    gemm_core(A, W, 8192, m0, n0, As, Ws, acc);

    const int tid = threadIdx.x;
    const int warp = tid >> 5, lane = tid & 31;
    const int gid = lane >> 2, tig = lane & 3;
    const int wm = warp & 3, wn = warp >> 2;

#pragma unroll
    for (int mt = 0; mt < 2; mt++)
#pragma unroll
        for (int hh = 0; hh < 2; hh++) {
            int m = m0 + wm * 32 + mt * 16 + gid + 8 * hh;
#pragma unroll
            for (int nt = 0; nt < 4; nt++)
#pragma unroll
                for (int cc = 0; cc < 2; cc++) {
                    int n = n0 + wn * 32 + nt * 8 + 2 * tig + cc;
                    out[(size_t)m * 512 + n] = acc[mt][nt][2 * hh + cc] + bias[n];
                }
        }
}

// ---------------------------------------------------------------------------
// Tensor-core flash attention with relative positions (R8 geometry:
// 64 queries/CTA, 128 threads, 87KB smem -> 2 CTAs/SM) with:
//  - exp(S) in Cp (warp-private rows): Ks never overwritten, 2 barriers/jt
//  - register-prefetch double buffering of next j-tile's K/V
// scores[i,j] = qu[i]·k[j] + Cp[i][j], Cp[i][j] = (Qv·P_slab^T)[i][63+j-i]
// ---------------------------------------------------------------------------
#define QST 68
// Ks 64 + Vs 64 + Ps 128 + Cp 64 rows, all stride QST
#define ATT_SMEM_U32 ((64 + 64 + 128 + 64) * QST)
#define ATT_SMEM_BYTES (ATT_SMEM_U32 * 4)

__global__ __launch_bounds__(128) void attn_mma(
    const float* __restrict__ qu, const float* __restrict__ qv,
    const float* __restrict__ kk, const float* __restrict__ vv,
    const float* __restrict__ pp, float* __restrict__ att)
{
    extern __shared__ __align__(16) uint32_t sh[];
    uint32_t* Ks = sh;                         // Qu staging, then K
    uint32_t* Vs = sh + 64 * QST;              // Qv staging, then V
    uint32_t* Ps = sh + 2 * 64 * QST;          // 128-row P slab
    uint32_t* CpU = sh + (2 * 64 + 128) * QST; // bias band / exp(S), 64 rows
    float*    Cp = (float*)CpU;

    const int tid = threadIdx.x;
    const int w = tid >> 5, lane = tid & 31;
    const int gid = lane >> 2, tig = lane & 3;
    const int i0 = blockIdx.x << 6;
    const int bh = blockIdx.y;
    const int h = bh & 7, b = bh >> 3;

    // Stage Q tiles (raw bits) into K/V buffers, extract frags, release.
#pragma unroll
    for (int r = 0; r < 8; r++) {
        int fi = tid + r * 128;
        int row = fi >> 4, c4 = (fi & 15) << 2;
        size_t g = ((size_t)bh * 1024 + i0 + row) * 64 + c4;
        *(uint4*)&Ks[row * QST + c4] = *(const uint4*)(qu + g);
        *(uint4*)&Vs[row * QST + c4] = *(const uint4*)(qv + g);
    }
    __syncthreads();

    uint32_t qua[8][4], qva[8][4];
#pragma unroll
    for (int ks = 0; ks < 8; ks++) {
        int rb = w * 16 + gid, cb = ks * 8 + tig;
        qua[ks][0] = Ks[rb * QST + cb];
        qua[ks][1] = Ks[(rb + 8) * QST + cb];
        qua[ks][2] = Ks[rb * QST + cb + 4];
        qua[ks][3] = Ks[(rb + 8) * QST + cb + 4];
        qva[ks][0] = Vs[rb * QST + cb];
        qva[ks][1] = Vs[(rb + 8) * QST + cb];
        qva[ks][2] = Vs[rb * QST + cb + 4];
        qva[ks][3] = Vs[(rb + 8) * QST + cb + 4];
    }

    float m_i[2] = {-1e30f, -1e30f}, l_i[2] = {0.f, 0.f};
    float oC[8][4];
#pragma unroll
    for (int nt = 0; nt < 8; nt++)
#pragma unroll
        for (int i = 0; i < 4; i++) oC[nt][i] = 0.f;

    // Prefetch K/V for jt=0 into registers
    uint4 pk[8], pv[8];
#pragma unroll
    for (int r = 0; r < 8; r++) {
        int fi = tid + r * 128;
        int row = fi >> 4, c4 = (fi & 15) << 2;
        size_t g = ((size_t)bh * 1024 + 0 + row) * 64 + c4;
        pk[r] = *(const uint4*)(kk + g);
        pv[r] = *(const uint4*)(vv + g);
    }

    // E band window for this warp's 16 rows: slab cols [48-16w, 126-16w]
    const int lo = 48 - w * 16, hi = 126 - w * 16;

    for (int jt = 0; jt < 16; jt++) {
        const int j0 = jt << 6;
        __syncthreads();   // prior iteration (and Q staging) done with smem

        // Commit prefetched K/V tiles (STS.128)
#pragma unroll
        for (int r = 0; r < 8; r++) {
            int fi = tid + r * 128;
            int row = fi >> 4, c4 = (fi & 15) << 2;
            *(uint4*)&Ks[row * QST + c4] = pk[r];
            *(uint4*)&Vs[row * QST + c4] = pv[r];
        }
        // Stage P slab rows rbase..rbase+127 (row 127 pads, clamped)
        const int rbase = 960 + j0 - i0;
#pragma unroll
        for (int r = 0; r < 16; r++) {
            int fi = tid + r * 128;
            int row = fi >> 4, c4 = (fi & 15) << 2;
            int prow = rbase + row;
            prow = prow > 2046 ? 2046 : prow;
            *(uint4*)&Ps[row * QST + c4] =
                *(const uint4*)(pp + ((size_t)h * 2047 + prow) * 64 + c4);
        }
        __syncthreads();

        // Prefetch next j-tile's K/V into registers (hidden under compute)
        if (jt + 1 < 16) {
            const int jn = (jt + 1) << 6;
#pragma unroll
            for (int r = 0; r < 8; r++) {
                int fi = tid + r * 128;
                int row = fi >> 4, c4 = (fi & 15) << 2;
                size_t g = ((size_t)bh * 1024 + jn + row) * 64 + c4;
                pk[r] = *(const uint4*)(kk + g);
                pv[r] = *(const uint4*)(vv + g);
            }
        }

        // E = Qv @ P_slab^T over band n-tiles; write compacted into Cp.
#pragma unroll
        for (int nt = 0; nt < 16; nt++) {
            if (nt * 8 + 7 < lo || nt * 8 > hi) continue;
            float e[4] = {0.f, 0.f, 0.f, 0.f};
#pragma unroll
            for (int ks = 0; ks < 8; ks++) {
                int rb = nt * 8 + gid, cb = ks * 8 + tig;
                mma8(e, qva[ks], Ps[rb * QST + cb], Ps[rb * QST + cb + 4]);
            }
            int er = w * 16 + gid, ec = nt * 8 + 2 * tig;
#pragma unroll
            for (int hh = 0; hh < 2; hh++) {
#pragma unroll
                for (int cc = 0; cc < 2; cc++) {
                    int row = er + 8 * hh;
                    int col = ec + cc - 63 + row;   // j index
                    if (col >= 0 && col < 64)
                        Cp[row * QST + col] = e[2 * hh + cc];
                }
            }
        }
        __syncwarp();   // Cp rows warp-private; cross-lane visibility

        // S1 = Qu @ K^T (8 n-tiles)
        float sC[8][4];
#pragma unroll
        for (int nt = 0; nt < 8; nt++)
#pragma unroll
            for (int i = 0; i < 4; i++) sC[nt][i] = 0.f;
#pragma unroll
        for (int ks = 0; ks < 8; ks++) {
#pragma unroll
            for (int nt = 0; nt < 8; nt++) {
                int rb = nt * 8 + gid, cb = ks * 8 + tig;
                mma8(sC[nt], qua[ks], Ks[rb * QST + cb], Ks[rb * QST + cb + 4]);
            }
        }

        // Online softmax; exp(S) written into Cp in place (warp-private)
#pragma unroll
        for (int hh = 0; hh < 2; hh++) {
            int qrow = w * 16 + gid + 8 * hh;
            float sv[16];
            float mx = -1e30f;
#pragma unroll
            for (int nt = 0; nt < 8; nt++) {
#pragma unroll
                for (int cc = 0; cc < 2; cc++) {
                    int jl = nt * 8 + 2 * tig + cc;
                    float s = sC[nt][2 * hh + cc] + Cp[qrow * QST + jl];
                    sv[nt * 2 + cc] = s;
                    mx = fmaxf(mx, s);
                }
            }
            mx = fmaxf(mx, __shfl_xor_sync(0xffffffffu, mx, 1));
            mx = fmaxf(mx, __shfl_xor_sync(0xffffffffu, mx, 2));
            float mn = fmaxf(m_i[hh], mx);
            float al = __expf(m_i[hh] - mn);
            float rs = 0.f;
#pragma unroll
            for (int t = 0; t < 16; t++) {
                float p = __expf(sv[t] - mn);
                rs += p;
                int nt = t >> 1, cc = t & 1;
                int jl = nt * 8 + 2 * tig + cc;
                Cp[qrow * QST + jl] = p;
            }
            rs += __shfl_xor_sync(0xffffffffu, rs, 1);
            rs += __shfl_xor_sync(0xffffffffu, rs, 2);
            l_i[hh] = l_i[hh] * al + rs;
            m_i[hh] = mn;
#pragma unroll
            for (int nt = 0; nt < 8; nt++) {
                oC[nt][2 * hh] *= al;
                oC[nt][2 * hh + 1] *= al;
            }
        }
        __syncwarp();   // exp rows warp-private

        // O += exp(S) @ V  (A from CpU, B from Vs)
#pragma unroll
        for (int ks = 0; ks < 8; ks++) {
            uint32_t a[4];
            int rb = w * 16 + gid, cb = ks * 8 + tig;
            a[0] = CpU[rb * QST + cb];
            a[1] = CpU[(rb + 8) * QST + cb];
            a[2] = CpU[rb * QST + cb + 4];
            a[3] = CpU[(rb + 8) * QST + cb + 4];
#pragma unroll
            for (int nt = 0; nt < 8; nt++) {
                uint32_t b0 = Vs[(ks * 8 + tig) * QST + nt * 8 + gid];
                uint32_t b1 = Vs[(ks * 8 + tig + 4) * QST + nt * 8 + gid];
                mma8(oC[nt], a, b0, b1);
            }
        }
    }

    // Write normalized output: att[b, t, h*64+d]
#pragma unroll
    for (int hh = 0; hh < 2; hh++) {
        int t = i0 + w * 16 + gid + 8 * hh;
        float inv = 1.f / l_i[hh];
#pragma unroll
        for (int nt = 0; nt < 8; nt++) {
            int d = nt * 8 + 2 * tig;
            size_t o = (((size_t)b * 1024 + t) * 8 + h) * 64 + d;
            att[o]     = oC[nt][2 * hh] * inv;
            att[o + 1] = oC[nt][2 * hh + 1] * inv;
        }
    }
}

// ---------------------------------------------------------------------------
extern "C" void kernel_launch(void* const* d_in, const int* in_sizes, int n_in,
                              void* d_out, int out_size)
{
    const float* query = (const float*)d_in[0];
    const float* key   = (const float*)d_in[1];
    const float* value = (const float*)d_in[2];
    const float* pos   = (const float*)d_in[3];
    const float* Wq    = (const float*)d_in[4];
    const float* bq    = (const float*)d_in[5];
    const float* Wk    = (const float*)d_in[6];
    const float* bk    = (const float*)d_in[7];
    const float* Wv    = (const float*)d_in[8];
    const float* bv_   = (const float*)d_in[9];
    const float* Wp    = (const float*)d_in[10];
    const float* Wo    = (const float*)d_in[11];
    const float* bo    = (const float*)d_in[12];
    const float* pbu   = (const float*)d_in[13];
    const float* pbv   = (const float*)d_in[14];

    float *qu_p, *qv_p, *k_p, *v_p, *p_p, *att_p;
    cudaGetSymbolAddress((void**)&qu_p,  g_qu);
    cudaGetSymbolAddress((void**)&qv_p,  g_qv);
    cudaGetSymbolAddress((void**)&k_p,   g_k);
    cudaGetSymbolAddress((void**)&v_p,   g_v);
    cudaGetSymbolAddress((void**)&p_p,   g_p);
    cudaGetSymbolAddress((void**)&att_p, g_att);

    cudaFuncSetAttribute(attn_mma,
                         cudaFuncAttributeMaxDynamicSharedMemorySize,
                         ATT_SMEM_BYTES);

    gemm_fused<<<dim3(8, 64, 4), 256>>>(
        query, key, value, pos, Wq, Wk, Wv, Wp,
        bq, bk, bv_, pbu, pbv,
        qu_p, qv_p, k_p, v_p, p_p);

    attn_mma<<<dim3(16, 64), dim3(128), ATT_SMEM_BYTES>>>(qu_p, qv_p, k_p, v_p,
                                                          p_p, att_p);

    gemm_out<<<dim3(8, 64), 256>>>(att_p, Wo, bo, (float*)d_out);
}

// round 13
// speedup vs baseline: 1.5831x; 1.3323x over previous
#include <cuda_runtime.h>
#include <cuda_fp16.h>
#include <cstdint>

// Problem constants: B=8, T=1024, F=512, H=8, D=64, P=2047
__device__ __half g_qu16[8 * 8 * 1024 * 64];  // [B,H,T,D] (q+bu)*scale, fp16
__device__ __half g_qv16[8 * 8 * 1024 * 64];  // [B,H,T,D] (q+bv)*scale, fp16
__device__ __half g_k16 [8 * 8 * 1024 * 64];  // [B,H,T,D] fp16
__device__ __half g_vt16[8 * 8 * 64 * 1024];  // [B,H,D,T] fp16 (transposed!)
__device__ __half g_p16 [8 * 2047 * 64];      // [H,P,D] fp16
__device__ float  g_att [8 * 1024 * 512];     // [B*T, F] fp32

// tf32 mma for the projection GEMMs
__device__ __forceinline__ void mma8(float c[4], const uint32_t a[4],
                                     uint32_t b0, uint32_t b1) {
    asm volatile(
        "mma.sync.aligned.m16n8k8.row.col.f32.tf32.tf32.f32 "
        "{%0,%1,%2,%3},{%4,%5,%6,%7},{%8,%9},{%0,%1,%2,%3};"
        : "+f"(c[0]), "+f"(c[1]), "+f"(c[2]), "+f"(c[3])
        : "r"(a[0]), "r"(a[1]), "r"(a[2]), "r"(a[3]), "r"(b0), "r"(b1));
}

// fp16 mma (f32 accumulate) for attention
__device__ __forceinline__ void mma16(float c[4], const uint32_t a[4],
                                      uint32_t b0, uint32_t b1) {
    asm volatile(
        "mma.sync.aligned.m16n8k16.row.col.f32.f16.f16.f32 "
        "{%0,%1,%2,%3},{%4,%5,%6,%7},{%8,%9},{%0,%1,%2,%3};"
        : "+f"(c[0]), "+f"(c[1]), "+f"(c[2]), "+f"(c[3])
        : "r"(a[0]), "r"(a[1]), "r"(a[2]), "r"(a[3]), "r"(b0), "r"(b1));
}

// Pack two fp32 into fp16x2 (lo -> low half), round-to-nearest.
__device__ __forceinline__ uint32_t pack2(float lo, float hi) {
    uint32_t u;
    asm("cvt.rn.f16x2.f32 %0, %1, %2;" : "=r"(u) : "f"(hi), "f"(lo));
    return u;
}

// Round-half-up into tf32: +2^12 on raw bits, hw mma truncates 13 bits.
__device__ __forceinline__ uint4 rnd4(uint4 v) {
    v.x += 0x1000u; v.y += 0x1000u; v.z += 0x1000u; v.w += 0x1000u;
    return v;
}

// ---------------------------------------------------------------------------
// TF32 NT GEMM core (unchanged, proven): C[m,n] = sum_k A[m,k]*W[n,k].
// ---------------------------------------------------------------------------
#define AST 36

__device__ __forceinline__ void gemm_core(
    const float* __restrict__ A, const float* __restrict__ W, int M,
    int m0, int n0, uint32_t* As, uint32_t* Ws, float acc[2][4][4])
{
    const int tid = threadIdx.x;
    const int warp = tid >> 5, lane = tid & 31;
    const int gid = lane >> 2, tig = lane & 3;
    const int wm = warp & 3, wn = warp >> 2;

#pragma unroll
    for (int mt = 0; mt < 2; mt++)
#pragma unroll
        for (int nt = 0; nt < 4; nt++)
#pragma unroll
            for (int i = 0; i < 4; i++) acc[mt][nt][i] = 0.f;

    uint4 pa[4], pw[2];
    const uint4 z4 = make_uint4(0u, 0u, 0u, 0u);

#pragma unroll
    for (int r = 0; r < 4; r++) {
        int ch = tid + r * 256;
        int row = ch >> 3, c4 = (ch & 7) << 2;
        int gm = m0 + row;
        pa[r] = (gm < M) ? rnd4(*(const uint4*)(A + (size_t)gm * 512 + c4)) : z4;
    }
#pragma unroll
    for (int r = 0; r < 2; r++) {
        int ch = tid + r * 256;
        int row = ch >> 3, c4 = (ch & 7) << 2;
        pw[r] = rnd4(*(const uint4*)(W + (size_t)(n0 + row) * 512 + c4));
    }

    for (int it = 0; it < 16; it++) {
#pragma unroll
        for (int r = 0; r < 4; r++) {
            int ch = tid + r * 256;
            int row = ch >> 3, c4 = (ch & 7) << 2;
            *(uint4*)&As[row * AST + c4] = pa[r];
        }
#pragma unroll
        for (int r = 0; r < 2; r++) {
            int ch = tid + r * 256;
            int row = ch >> 3, c4 = (ch & 7) << 2;
            *(uint4*)&Ws[row * AST + c4] = pw[r];
        }
        __syncthreads();

        if (it + 1 < 16) {
            int k0 = (it + 1) * 32;
#pragma unroll
            for (int r = 0; r < 4; r++) {
                int ch = tid + r * 256;
                int row = ch >> 3, c4 = (ch & 7) << 2;
                int gm = m0 + row;
                pa[r] = (gm < M)
                    ? rnd4(*(const uint4*)(A + (size_t)gm * 512 + k0 + c4)) : z4;
            }
#pragma unroll
            for (int r = 0; r < 2; r++) {
                int ch = tid + r * 256;
                int row = ch >> 3, c4 = (ch & 7) << 2;
                pw[r] = rnd4(*(const uint4*)(W + (size_t)(n0 + row) * 512 + k0 + c4));
            }
        }

#pragma unroll
        for (int ks = 0; ks < 4; ks++) {
            uint32_t a[2][4];
#pragma unroll
            for (int mt = 0; mt < 2; mt++) {
                int rb = wm * 32 + mt * 16 + gid, cb = ks * 8 + tig;
                a[mt][0] = As[rb * AST + cb];
                a[mt][1] = As[(rb + 8) * AST + cb];
                a[mt][2] = As[rb * AST + cb + 4];
                a[mt][3] = As[(rb + 8) * AST + cb + 4];
            }
#pragma unroll
            for (int nt = 0; nt < 4; nt++) {
                int nb = wn * 32 + nt * 8 + gid;
                uint32_t b0 = Ws[nb * AST + ks * 8 + tig];
                uint32_t b1 = Ws[nb * AST + ks * 8 + tig + 4];
                mma8(acc[0][nt], a[0], b0, b1);
                mma8(acc[1][nt], a[1], b0, b1);
            }
        }
        __syncthreads();
    }
}

// Fused Q/K/V/P projection GEMM; fp16 pair-packed outputs (V transposed).
__global__ __launch_bounds__(256) void gemm_fused(
    const float* __restrict__ query, const float* __restrict__ key,
    const float* __restrict__ value, const float* __restrict__ pos,
    const float* __restrict__ Wq, const float* __restrict__ Wk,
    const float* __restrict__ Wv, const float* __restrict__ Wp,
    const float* __restrict__ bq, const float* __restrict__ bk,
    const float* __restrict__ bvb, const float* __restrict__ bu,
    const float* __restrict__ bvv,
    __half* __restrict__ o_qu, __half* __restrict__ o_qv,
    __half* __restrict__ o_k, __half* __restrict__ o_v,
    __half* __restrict__ o_p)
{
    __shared__ __align__(16) uint32_t As[128 * AST];
    __shared__ __align__(16) uint32_t Ws[64 * AST];

    const int z = blockIdx.z;
    const float *A, *W;
    int M;
    if (z == 0)      { A = query; W = Wq; M = 8192; }
    else if (z == 1) { A = key;   W = Wk; M = 8192; }
    else if (z == 2) { A = value; W = Wv; M = 8192; }
    else             { A = pos;   W = Wp; M = 2047; }

    const int m0 = blockIdx.y * 128, n0 = blockIdx.x * 64;
    if (m0 >= M) return;

    float acc[2][4][4];
    gemm_core(A, W, M, m0, n0, As, Ws, acc);

    const int tid = threadIdx.x;
    const int warp = tid >> 5, lane = tid & 31;
    const int gid = lane >> 2, tig = lane & 3;
    const int wm = warp & 3, wn = warp >> 2;
    const float scale = 0.125f;

#pragma unroll
    for (int mt = 0; mt < 2; mt++) {
#pragma unroll
        for (int hh = 0; hh < 2; hh++) {
            int m = m0 + wm * 32 + mt * 16 + gid + 8 * hh;
            if (m >= M) continue;
#pragma unroll
            for (int nt = 0; nt < 4; nt++) {
                int n = n0 + wn * 32 + nt * 8 + 2 * tig;   // even, pair (n,n+1)
                float v0 = acc[mt][nt][2 * hh];
                float v1 = acc[mt][nt][2 * hh + 1];
                if (z == 0) {
                    int b = m >> 10, t = m & 1023, h = n >> 6, d = n & 63;
                    float b0 = v0 + bq[n], b1 = v1 + bq[n + 1];
                    size_t i32 = ((((size_t)(b * 8 + h) << 10) + t) << 5) + (d >> 1);
                    ((uint32_t*)o_qu)[i32] =
                        pack2((b0 + bu[n]) * scale, (b1 + bu[n + 1]) * scale);
                    ((uint32_t*)o_qv)[i32] =
                        pack2((b0 + bvv[n]) * scale, (b1 + bvv[n + 1]) * scale);
                } else if (z == 1) {
                    int b = m >> 10, t = m & 1023, h = n >> 6, d = n & 63;
                    size_t i32 = ((((size_t)(b * 8 + h) << 10) + t) << 5) + (d >> 1);
                    ((uint32_t*)o_k)[i32] = pack2(v0 + bk[n], v1 + bk[n + 1]);
                } else if (z == 2) {
                    int b = m >> 10, t = m & 1023, h = n >> 6, d = n & 63;
                    // transposed: [bh][d][t]
                    o_v[((size_t)(b * 8 + h) * 64 + d) * 1024 + t] =
                        __float2half_rn(v0 + bvb[n]);
                    o_v[((size_t)(b * 8 + h) * 64 + d + 1) * 1024 + t] =
                        __float2half_rn(v1 + bvb[n + 1]);
                } else {
                    int h = n >> 6, d = n & 63;
                    size_t i32 = (((size_t)h * 2047 + m) << 5) + (d >> 1);
                    ((uint32_t*)o_p)[i32] = pack2(v0, v1);
                }
            }
        }
    }
}

// Output projection GEMM: d_out = att @ Wo^T + bo (fp32, unchanged).
__global__ __launch_bounds__(256) void gemm_out(
    const float* __restrict__ A, const float* __restrict__ W,
    const float* __restrict__ bias, float* __restrict__ out)
{
    __shared__ __align__(16) uint32_t As[128 * AST];
    __shared__ __align__(16) uint32_t Ws[64 * AST];

    const int m0 = blockIdx.y * 128, n0 = blockIdx.x * 64;
    float acc[2][4][4];
    gemm_core(A, W, 8192, m0, n0, As, Ws, acc);

    const int tid = threadIdx.x;
    const int warp = tid >> 5, lane = tid & 31;
    const int gid = lane >> 2, tig = lane & 3;
    const int wm = warp & 3, wn = warp >> 2;

#pragma unroll
    for (int mt = 0; mt < 2; mt++)
#pragma unroll
        for (int hh = 0; hh < 2; hh++) {
            int m = m0 + wm * 32 + mt * 16 + gid + 8 * hh;
#pragma unroll
            for (int nt = 0; nt < 4; nt++)
#pragma unroll
                for (int cc = 0; cc < 2; cc++) {
                    int n = n0 + wn * 32 + nt * 8 + 2 * tig + cc;
                    out[(size_t)m * 512 + n] = acc[mt][nt][2 * hh + cc] + bias[n];
                }
        }
}

// ---------------------------------------------------------------------------
// FP16 tensor-core flash attention with relative positions.
// m16n8k16 f16 mma, f32 accum. 64 queries/CTA, 128 threads, 63.5KB smem
// -> 3 CTAs/SM. K/V register-prefetch; exp(S) packed fp16 in Ep.
// scores[i,j] = qu[i]·k[j] + Cp[i][j], Cp[i][j] = (Qv·P_slab^T)[i][63+j-i]
// ---------------------------------------------------------------------------
#define ST 36     // u32 stride of fp16 tiles (64 halves = 32 u32 + pad)
#define CST 68    // f32 stride of Cp band
#define ATT_SMEM_U32 (320 * ST + 64 * CST)
#define ATT_SMEM_BYTES (ATT_SMEM_U32 * 4)

__global__ __launch_bounds__(128, 3) void attn_mma(
    const __half* __restrict__ qu, const __half* __restrict__ qv,
    const __half* __restrict__ kk, const __half* __restrict__ vt,
    const __half* __restrict__ pp, float* __restrict__ att)
{
    extern __shared__ __align__(16) uint32_t sh[];
    uint32_t* Ks = sh;                    // Qu staging, then K  (64 rows)
    uint32_t* Vt = sh + 64 * ST;          // Qv staging, then V^T (64 rows=d)
    uint32_t* Ps = sh + 2 * 64 * ST;      // P slab (128 rows)
    uint32_t* Ep = sh + 4 * 64 * ST;      // exp(S) fp16 pairs (64 rows)
    float*    Cp = (float*)(sh + 5 * 64 * ST);   // bias band f32 (64 x CST)

    const int tid = threadIdx.x;
    const int w = tid >> 5, lane = tid & 31;
    const int gid = lane >> 2, tig = lane & 3;
    const int i0 = blockIdx.x << 6;
    const int bh = blockIdx.y;
    const int h = bh & 7, b = bh >> 3;

    // Stage Qu -> Ks area, Qv -> Vt area (fp16, 4 uint4 per thread each)
#pragma unroll
    for (int r = 0; r < 4; r++) {
        int fi = tid + r * 128;
        int row = fi >> 3, hc = (fi & 7) << 3;     // half offset in row
        size_t g = ((size_t)bh * 1024 + i0 + row) * 64 + hc;
        *(uint4*)&Ks[row * ST + ((fi & 7) << 2)] = *(const uint4*)(qu + g);
        *(uint4*)&Vt[row * ST + ((fi & 7) << 2)] = *(const uint4*)(qv + g);
    }
    __syncthreads();

    uint32_t qua[4][4], qva[4][4];
#pragma unroll
    for (int ks = 0; ks < 4; ks++) {
        int rb = w * 16 + gid, cb = ks * 8 + tig;
        qua[ks][0] = Ks[rb * ST + cb];
        qua[ks][1] = Ks[(rb + 8) * ST + cb];
        qua[ks][2] = Ks[rb * ST + cb + 4];
        qua[ks][3] = Ks[(rb + 8) * ST + cb + 4];
        qva[ks][0] = Vt[rb * ST + cb];
        qva[ks][1] = Vt[(rb + 8) * ST + cb];
        qva[ks][2] = Vt[rb * ST + cb + 4];
        qva[ks][3] = Vt[(rb + 8) * ST + cb + 4];
    }

    float m_i[2] = {-1e30f, -1e30f}, l_i[2] = {0.f, 0.f};
    float oC[8][4];
#pragma unroll
    for (int nt = 0; nt < 8; nt++)
#pragma unroll
        for (int i = 0; i < 4; i++) oC[nt][i] = 0.f;

    // Prefetch K/V for jt=0 (K: [bh][t][d]; V: transposed [bh][d][t])
    uint4 pk[4], pv[4];
#pragma unroll
    for (int r = 0; r < 4; r++) {
        int fi = tid + r * 128;
        int row = fi >> 3, hc = (fi & 7) << 3;
        pk[r] = *(const uint4*)(kk + ((size_t)bh * 1024 + row) * 64 + hc);
        pv[r] = *(const uint4*)(vt + ((size_t)bh * 64 + row) * 1024 + hc);
    }

    // E band window for this warp's 16 rows: slab cols [48-16w, 126-16w]
    const int lo = 48 - w * 16, hi = 126 - w * 16;

    for (int jt = 0; jt < 16; jt++) {
        const int j0 = jt << 6;
        __syncthreads();   // prior iteration (and Q staging) done with smem

        // Commit prefetched K/V tiles
#pragma unroll
        for (int r = 0; r < 4; r++) {
            int fi = tid + r * 128;
            int row = fi >> 3, c4 = (fi & 7) << 2;
            *(uint4*)&Ks[row * ST + c4] = pk[r];
            *(uint4*)&Vt[row * ST + c4] = pv[r];
        }
        // Stage P slab: 128 rows, 8 uint4 per thread
        const int rbase = 960 + j0 - i0;
#pragma unroll
        for (int r = 0; r < 8; r++) {
            int fi = tid + r * 128;
            int row = fi >> 3, hc = (fi & 7) << 3;
            int prow = rbase + row;
            prow = prow > 2046 ? 2046 : prow;
            *(uint4*)&Ps[row * ST + ((fi & 7) << 2)] =
                *(const uint4*)(pp + ((size_t)h * 2047 + prow) * 64 + hc);
        }
        __syncthreads();

        // Prefetch next j-tile's K/V (latency hidden under compute)
        if (jt + 1 < 16) {
            const int jn = (jt + 1) << 6;
#pragma unroll
            for (int r = 0; r < 4; r++) {
                int fi = tid + r * 128;
                int row = fi >> 3, hc = (fi & 7) << 3;
                pk[r] = *(const uint4*)(kk + ((size_t)bh * 1024 + jn + row) * 64 + hc);
                pv[r] = *(const uint4*)(vt + ((size_t)bh * 64 + row) * 1024 + jn + hc);
            }
        }

        // E = Qv @ P_slab^T over band n-tiles; write compacted f32 into Cp.
#pragma unroll
        for (int nt = 0; nt < 16; nt++) {
            if (nt * 8 + 7 < lo || nt * 8 > hi) continue;
            float e[4] = {0.f, 0.f, 0.f, 0.f};
#pragma unroll
            for (int ks = 0; ks < 4; ks++) {
                int rb = nt * 8 + gid, cb = ks * 8 + tig;
                mma16(e, qva[ks], Ps[rb * ST + cb], Ps[rb * ST + cb + 4]);
            }
            int er = w * 16 + gid, ec = nt * 8 + 2 * tig;
#pragma unroll
            for (int hh = 0; hh < 2; hh++) {
#pragma unroll
                for (int cc = 0; cc < 2; cc++) {
                    int row = er + 8 * hh;
                    int col = ec + cc - 63 + row;   // j index
                    if (col >= 0 && col < 64)
                        Cp[row * CST + col] = e[2 * hh + cc];
                }
            }
        }
        __syncwarp();   // Cp rows warp-private

        // S1 = Qu @ K^T (8 n-tiles, 4 k-steps)
        float sC[8][4];
#pragma unroll
        for (int nt = 0; nt < 8; nt++)
#pragma unroll
            for (int i = 0; i < 4; i++) sC[nt][i] = 0.f;
#pragma unroll
        for (int ks = 0; ks < 4; ks++) {
#pragma unroll
            for (int nt = 0; nt < 8; nt++) {
                int rb = nt * 8 + gid, cb = ks * 8 + tig;
                mma16(sC[nt], qua[ks], Ks[rb * ST + cb], Ks[rb * ST + cb + 4]);
            }
        }

        // Online softmax; exp(S) packed fp16 pairs into Ep
#pragma unroll
        for (int hh = 0; hh < 2; hh++) {
            int qrow = w * 16 + gid + 8 * hh;
            float sv[16];
            float mx = -1e30f;
#pragma unroll
            for (int nt = 0; nt < 8; nt++) {
#pragma unroll
                for (int cc = 0; cc < 2; cc++) {
                    int jl = nt * 8 + 2 * tig + cc;
                    float s = sC[nt][2 * hh + cc] + Cp[qrow * CST + jl];
                    sv[nt * 2 + cc] = s;
                    mx = fmaxf(mx, s);
                }
            }
            mx = fmaxf(mx, __shfl_xor_sync(0xffffffffu, mx, 1));
            mx = fmaxf(mx, __shfl_xor_sync(0xffffffffu, mx, 2));
            float mn = fmaxf(m_i[hh], mx);
            float al = __expf(m_i[hh] - mn);
            float rs = 0.f;
#pragma unroll
            for (int nt = 0; nt < 8; nt++) {
                float p0 = __expf(sv[nt * 2] - mn);
                float p1 = __expf(sv[nt * 2 + 1] - mn);
                rs += p0 + p1;
                Ep[qrow * ST + nt * 4 + tig] = pack2(p0, p1);
            }
            rs += __shfl_xor_sync(0xffffffffu, rs, 1);
            rs += __shfl_xor_sync(0xffffffffu, rs, 2);
            l_i[hh] = l_i[hh] * al + rs;
            m_i[hh] = mn;
#pragma unroll
            for (int nt = 0; nt < 8; nt++) {
                oC[nt][2 * hh] *= al;
                oC[nt][2 * hh + 1] *= al;
            }
        }
        __syncwarp();   // Ep rows warp-private

        // O += exp(S) @ V   (A from Ep, B from Vt)
#pragma unroll
        for (int ks = 0; ks < 4; ks++) {
            uint32_t a[4];
            int rb = w * 16 + gid, cb = ks * 8 + tig;
            a[0] = Ep[rb * ST + cb];
            a[1] = Ep[(rb + 8) * ST + cb];
            a[2] = Ep[rb * ST + cb + 4];
            a[3] = Ep[(rb + 8) * ST + cb + 4];
#pragma unroll
            for (int nt = 0; nt < 8; nt++) {
                int nb = nt * 8 + gid;
                uint32_t b0 = Vt[nb * ST + cb];
                uint32_t b1 = Vt[nb * ST + cb + 4];
                mma16(oC[nt], a, b0, b1);
            }
        }
    }

    // Write normalized output: att[b, t, h*64+d]
#pragma unroll
    for (int hh = 0; hh < 2; hh++) {
        int t = i0 + w * 16 + gid + 8 * hh;
        float inv = 1.f / l_i[hh];
#pragma unroll
        for (int nt = 0; nt < 8; nt++) {
            int d = nt * 8 + 2 * tig;
            size_t o = (((size_t)b * 1024 + t) * 8 + h) * 64 + d;
            att[o]     = oC[nt][2 * hh] * inv;
            att[o + 1] = oC[nt][2 * hh + 1] * inv;
        }
    }
}

// ---------------------------------------------------------------------------
extern "C" void kernel_launch(void* const* d_in, const int* in_sizes, int n_in,
                              void* d_out, int out_size)
{
    const float* query = (const float*)d_in[0];
    const float* key   = (const float*)d_in[1];
    const float* value = (const float*)d_in[2];
    const float* pos   = (const float*)d_in[3];
    const float* Wq    = (const float*)d_in[4];
    const float* bq    = (const float*)d_in[5];
    const float* Wk    = (const float*)d_in[6];
    const float* bk    = (const float*)d_in[7];
    const float* Wv    = (const float*)d_in[8];
    const float* bv_   = (const float*)d_in[9];
    const float* Wp    = (const float*)d_in[10];
    const float* Wo    = (const float*)d_in[11];
    const float* bo    = (const float*)d_in[12];
    const float* pbu   = (const float*)d_in[13];
    const float* pbv   = (const float*)d_in[14];

    __half *qu_p, *qv_p, *k_p, *vt_p, *p_p;
    float *att_p;
    cudaGetSymbolAddress((void**)&qu_p,  g_qu16);
    cudaGetSymbolAddress((void**)&qv_p,  g_qv16);
    cudaGetSymbolAddress((void**)&k_p,   g_k16);
    cudaGetSymbolAddress((void**)&vt_p,  g_vt16);
    cudaGetSymbolAddress((void**)&p_p,   g_p16);
    cudaGetSymbolAddress((void**)&att_p, g_att);

    cudaFuncSetAttribute(attn_mma,
                         cudaFuncAttributeMaxDynamicSharedMemorySize,
                         ATT_SMEM_BYTES);

    gemm_fused<<<dim3(8, 64, 4), 256>>>(
        query, key, value, pos, Wq, Wk, Wv, Wp,
        bq, bk, bv_, pbu, pbv,
        qu_p, qv_p, k_p, vt_p, p_p);

    attn_mma<<<dim3(16, 64), dim3(128), ATT_SMEM_BYTES>>>(qu_p, qv_p, k_p, vt_p,
                                                          p_p, att_p);

    gemm_out<<<dim3(8, 64), 256>>>(att_p, Wo, bo, (float*)d_out);
}

// round 15
// speedup vs baseline: 1.8342x; 1.1586x over previous
#include <cuda_runtime.h>
#include <cuda_fp16.h>
#include <cstdint>

// Problem constants: B=8, T=1024, F=512, H=8, D=64, P=2047
__device__ __half g_qu16[8 * 8 * 1024 * 64];  // [B,H,T,D] (q+bu)*scale, fp16
__device__ __half g_qv16[8 * 8 * 1024 * 64];  // [B,H,T,D] (q+bv)*scale, fp16
__device__ __half g_k16 [8 * 8 * 1024 * 64];  // [B,H,T,D] fp16
__device__ __half g_vt16[8 * 8 * 64 * 1024];  // [B,H,D,T] fp16 (transposed!)
__device__ __half g_p16 [8 * 2047 * 64];      // [H,P,D] fp16
__device__ __half g_att16[8 * 1024 * 512];    // [B*T, F] fp16

// fp16 mma (f32 accumulate)
__device__ __forceinline__ void mma16(float c[4], const uint32_t a[4],
                                      uint32_t b0, uint32_t b1) {
    asm volatile(
        "mma.sync.aligned.m16n8k16.row.col.f32.f16.f16.f32 "
        "{%0,%1,%2,%3},{%4,%5,%6,%7},{%8,%9},{%0,%1,%2,%3};"
        : "+f"(c[0]), "+f"(c[1]), "+f"(c[2]), "+f"(c[3])
        : "r"(a[0]), "r"(a[1]), "r"(a[2]), "r"(a[3]), "r"(b0), "r"(b1));
}

// Pack two fp32 into fp16x2 (lo -> low half), round-to-nearest.
__device__ __forceinline__ uint32_t pack2(float lo, float hi) {
    uint32_t u;
    asm("cvt.rn.f16x2.f32 %0, %1, %2;" : "=r"(u) : "f"(hi), "f"(lo));
    return u;
}

// Convert 8 consecutive fp32 at src into one uint4 of 8 fp16.
__device__ __forceinline__ uint4 cvt8(const float* src) {
    float4 f0 = *(const float4*)src;
    float4 f1 = *(const float4*)(src + 4);
    uint4 o;
    o.x = pack2(f0.x, f0.y); o.y = pack2(f0.z, f0.w);
    o.z = pack2(f1.x, f1.y); o.w = pack2(f1.z, f1.w);
    return o;
}

// ---------------------------------------------------------------------------
// FP16 NT GEMM core: C[m,n] = sum_k A[m,k]*W[n,k], K=N=512, fp32 accum.
// Block tile 128x64, BK=64 (8 iters), register-prefetch double buffering.
// 256 threads = 8 warps (4m x 2n), warp tile 32x32, m16n8k16.
// A source is fp32 (converted on stage) or fp16 (direct).
// ---------------------------------------------------------------------------
#define HST 36   // u32 stride per row (32 used = 64 halves)

template <bool A_IS_HALF>
__device__ __forceinline__ void hgemm_core(
    const void* __restrict__ Asrc, const float* __restrict__ W, int M,
    int m0, int n0, uint32_t* As, uint32_t* Ws, float acc[2][4][4])
{
    const int tid = threadIdx.x;
    const int warp = tid >> 5, lane = tid & 31;
    const int gid = lane >> 2, tig = lane & 3;
    const int wm = warp & 3, wn = warp >> 2;

#pragma unroll
    for (int mt = 0; mt < 2; mt++)
#pragma unroll
        for (int nt = 0; nt < 4; nt++)
#pragma unroll
            for (int i = 0; i < 4; i++) acc[mt][nt][i] = 0.f;

    uint4 pa[4], pw[2];
    const uint4 z4 = make_uint4(0u, 0u, 0u, 0u);

    auto ldA = [&](int k0, int r) -> uint4 {
        int ch = tid + r * 256;
        int row = ch >> 3, h8 = (ch & 7) << 3;
        int gm = m0 + row;
        if (gm >= M) return z4;
        if (A_IS_HALF)
            return *(const uint4*)((const __half*)Asrc + (size_t)gm * 512 + k0 + h8);
        else
            return cvt8((const float*)Asrc + (size_t)gm * 512 + k0 + h8);
    };
    auto ldW = [&](int k0, int r) -> uint4 {
        int ch = tid + r * 256;
        int row = ch >> 3, h8 = (ch & 7) << 3;
        return cvt8(W + (size_t)(n0 + row) * 512 + k0 + h8);
    };

#pragma unroll
    for (int r = 0; r < 4; r++) pa[r] = ldA(0, r);
#pragma unroll
    for (int r = 0; r < 2; r++) pw[r] = ldW(0, r);

    for (int it = 0; it < 8; it++) {
        // Commit prefetched tiles (STS.128)
#pragma unroll
        for (int r = 0; r < 4; r++) {
            int ch = tid + r * 256;
            int row = ch >> 3, c4 = (ch & 7) << 2;
            *(uint4*)&As[row * HST + c4] = pa[r];
        }
#pragma unroll
        for (int r = 0; r < 2; r++) {
            int ch = tid + r * 256;
            int row = ch >> 3, c4 = (ch & 7) << 2;
            *(uint4*)&Ws[row * HST + c4] = pw[r];
        }
        __syncthreads();

        // Prefetch next tile (latency overlapped with mma)
        if (it + 1 < 8) {
            int k0 = (it + 1) * 64;
#pragma unroll
            for (int r = 0; r < 4; r++) pa[r] = ldA(k0, r);
#pragma unroll
            for (int r = 0; r < 2; r++) pw[r] = ldW(k0, r);
        }

        // Compute: 4 k-steps of 16
#pragma unroll
        for (int ks = 0; ks < 4; ks++) {
            uint32_t a[2][4];
#pragma unroll
            for (int mt = 0; mt < 2; mt++) {
                int rb = wm * 32 + mt * 16 + gid, cb = ks * 8 + tig;
                a[mt][0] = As[rb * HST + cb];
                a[mt][1] = As[(rb + 8) * HST + cb];
                a[mt][2] = As[rb * HST + cb + 4];
                a[mt][3] = As[(rb + 8) * HST + cb + 4];
            }
#pragma unroll
            for (int nt = 0; nt < 4; nt++) {
                int nb = wn * 32 + nt * 8 + gid;
                uint32_t b0 = Ws[nb * HST + ks * 8 + tig];
                uint32_t b1 = Ws[nb * HST + ks * 8 + tig + 4];
                mma16(acc[0][nt], a[0], b0, b1);
                mma16(acc[1][nt], a[1], b0, b1);
            }
        }
        __syncthreads();
    }
}

// Fused Q/K/V/P projection GEMM; fp16 pair-packed outputs (V transposed).
__global__ __launch_bounds__(256) void gemm_fused(
    const float* __restrict__ query, const float* __restrict__ key,
    const float* __restrict__ value, const float* __restrict__ pos,
    const float* __restrict__ Wq, const float* __restrict__ Wk,
    const float* __restrict__ Wv, const float* __restrict__ Wp,
    const float* __restrict__ bq, const float* __restrict__ bk,
    const float* __restrict__ bvb, const float* __restrict__ bu,
    const float* __restrict__ bvv,
    __half* __restrict__ o_qu, __half* __restrict__ o_qv,
    __half* __restrict__ o_k, __half* __restrict__ o_v,
    __half* __restrict__ o_p)
{
    __shared__ __align__(16) uint32_t As[128 * HST];
    __shared__ __align__(16) uint32_t Ws[64 * HST];

    const int z = blockIdx.z;
    const float *A, *W;
    int M;
    if (z == 0)      { A = query; W = Wq; M = 8192; }
    else if (z == 1) { A = key;   W = Wk; M = 8192; }
    else if (z == 2) { A = value; W = Wv; M = 8192; }
    else             { A = pos;   W = Wp; M = 2047; }

    const int m0 = blockIdx.y * 128, n0 = blockIdx.x * 64;
    if (m0 >= M) return;

    float acc[2][4][4];
    hgemm_core<false>(A, W, M, m0, n0, As, Ws, acc);

    const int tid = threadIdx.x;
    const int warp = tid >> 5, lane = tid & 31;
    const int gid = lane >> 2, tig = lane & 3;
    const int wm = warp & 3, wn = warp >> 2;
    const float scale = 0.125f;

#pragma unroll
    for (int mt = 0; mt < 2; mt++) {
#pragma unroll
        for (int hh = 0; hh < 2; hh++) {
            int m = m0 + wm * 32 + mt * 16 + gid + 8 * hh;
            if (m >= M) continue;
#pragma unroll
            for (int nt = 0; nt < 4; nt++) {
                int n = n0 + wn * 32 + nt * 8 + 2 * tig;   // even, pair (n,n+1)
                float v0 = acc[mt][nt][2 * hh];
                float v1 = acc[mt][nt][2 * hh + 1];
                if (z == 0) {
                    int b = m >> 10, t = m & 1023, h = n >> 6, d = n & 63;
                    float b0 = v0 + bq[n], b1 = v1 + bq[n + 1];
                    size_t i32 = ((((size_t)(b * 8 + h) << 10) + t) << 5) + (d >> 1);
                    ((uint32_t*)o_qu)[i32] =
                        pack2((b0 + bu[n]) * scale, (b1 + bu[n + 1]) * scale);
                    ((uint32_t*)o_qv)[i32] =
                        pack2((b0 + bvv[n]) * scale, (b1 + bvv[n + 1]) * scale);
                } else if (z == 1) {
                    int b = m >> 10, t = m & 1023, h = n >> 6, d = n & 63;
                    size_t i32 = ((((size_t)(b * 8 + h) << 10) + t) << 5) + (d >> 1);
                    ((uint32_t*)o_k)[i32] = pack2(v0 + bk[n], v1 + bk[n + 1]);
                } else if (z == 2) {
                    int b = m >> 10, t = m & 1023, h = n >> 6, d = n & 63;
                    // transposed: [bh][d][t]
                    o_v[((size_t)(b * 8 + h) * 64 + d) * 1024 + t] =
                        __float2half_rn(v0 + bvb[n]);
                    o_v[((size_t)(b * 8 + h) * 64 + d + 1) * 1024 + t] =
                        __float2half_rn(v1 + bvb[n + 1]);
                } else {
                    int h = n >> 6, d = n & 63;
                    size_t i32 = (((size_t)h * 2047 + m) << 5) + (d >> 1);
                    ((uint32_t*)o_p)[i32] = pack2(v0, v1);
                }
            }
        }
    }
}

// Output projection GEMM: d_out = att16 @ Wo^T + bo (A fp16, W converted).
__global__ __launch_bounds__(256) void gemm_out(
    const __half* __restrict__ A16, const float* __restrict__ W,
    const float* __restrict__ bias, float* __restrict__ out)
{
    __shared__ __align__(16) uint32_t As[128 * HST];
    __shared__ __align__(16) uint32_t Ws[64 * HST];

    const int m0 = blockIdx.y * 128, n0 = blockIdx.x * 64;
    float acc[2][4][4];
    hgemm_core<true>(A16, W, 8192, m0, n0, As, Ws, acc);

    const int tid = threadIdx.x;
    const int warp = tid >> 5, lane = tid & 31;
    const int gid = lane >> 2, tig = lane & 3;
    const int wm = warp & 3, wn = warp >> 2;

#pragma unroll
    for (int mt = 0; mt < 2; mt++)
#pragma unroll
        for (int hh = 0; hh < 2; hh++) {
            int m = m0 + wm * 32 + mt * 16 + gid + 8 * hh;
#pragma unroll
            for (int nt = 0; nt < 4; nt++)
#pragma unroll
                for (int cc = 0; cc < 2; cc++) {
                    int n = n0 + wn * 32 + nt * 8 + 2 * tig + cc;
                    out[(size_t)m * 512 + n] = acc[mt][nt][2 * hh + cc] + bias[n];
                }
        }
}

// ---------------------------------------------------------------------------
// FP16 tensor-core flash attention (proven R13 kernel; output now fp16).
// ---------------------------------------------------------------------------
#define ST 36     // u32 stride of fp16 tiles
#define CST 68    // f32 stride of Cp band
#define ATT_SMEM_U32 (320 * ST + 64 * CST)
#define ATT_SMEM_BYTES (ATT_SMEM_U32 * 4)

__global__ __launch_bounds__(128, 3) void attn_mma(
    const __half* __restrict__ qu, const __half* __restrict__ qv,
    const __half* __restrict__ kk, const __half* __restrict__ vt,
    const __half* __restrict__ pp, __half* __restrict__ att)
{
    extern __shared__ __align__(16) uint32_t sh[];
    uint32_t* Ks = sh;                    // Qu staging, then K  (64 rows)
    uint32_t* Vt = sh + 64 * ST;          // Qv staging, then V^T (64 rows=d)
    uint32_t* Ps = sh + 2 * 64 * ST;      // P slab (128 rows)
    uint32_t* Ep = sh + 4 * 64 * ST;      // exp(S) fp16 pairs (64 rows)
    float*    Cp = (float*)(sh + 5 * 64 * ST);   // bias band f32 (64 x CST)

    const int tid = threadIdx.x;
    const int w = tid >> 5, lane = tid & 31;
    const int gid = lane >> 2, tig = lane & 3;
    const int i0 = blockIdx.x << 6;
    const int bh = blockIdx.y;
    const int h = bh & 7, b = bh >> 3;

    // Stage Qu -> Ks area, Qv -> Vt area
#pragma unroll
    for (int r = 0; r < 4; r++) {
        int fi = tid + r * 128;
        int row = fi >> 3, hc = (fi & 7) << 3;
        size_t g = ((size_t)bh * 1024 + i0 + row) * 64 + hc;
        *(uint4*)&Ks[row * ST + ((fi & 7) << 2)] = *(const uint4*)(qu + g);
        *(uint4*)&Vt[row * ST + ((fi & 7) << 2)] = *(const uint4*)(qv + g);
    }
    __syncthreads();

    uint32_t qua[4][4], qva[4][4];
#pragma unroll
    for (int ks = 0; ks < 4; ks++) {
        int rb = w * 16 + gid, cb = ks * 8 + tig;
        qua[ks][0] = Ks[rb * ST + cb];
        qua[ks][1] = Ks[(rb + 8) * ST + cb];
        qua[ks][2] = Ks[rb * ST + cb + 4];
        qua[ks][3] = Ks[(rb + 8) * ST + cb + 4];
        qva[ks][0] = Vt[rb * ST + cb];
        qva[ks][1] = Vt[(rb + 8) * ST + cb];
        qva[ks][2] = Vt[rb * ST + cb + 4];
        qva[ks][3] = Vt[(rb + 8) * ST + cb + 4];
    }

    float m_i[2] = {-1e30f, -1e30f}, l_i[2] = {0.f, 0.f};
    float oC[8][4];
#pragma unroll
    for (int nt = 0; nt < 8; nt++)
#pragma unroll
        for (int i = 0; i < 4; i++) oC[nt][i] = 0.f;

    // Prefetch K/V for jt=0 (K: [bh][t][d]; V: transposed [bh][d][t])
    uint4 pk[4], pv[4];
#pragma unroll
    for (int r = 0; r < 4; r++) {
        int fi = tid + r * 128;
        int row = fi >> 3, hc = (fi & 7) << 3;
        pk[r] = *(const uint4*)(kk + ((size_t)bh * 1024 + row) * 64 + hc);
        pv[r] = *(const uint4*)(vt + ((size_t)bh * 64 + row) * 1024 + hc);
    }

    // E band window for this warp's 16 rows: slab cols [48-16w, 126-16w]
    const int lo = 48 - w * 16, hi = 126 - w * 16;

    for (int jt = 0; jt < 16; jt++) {
        const int j0 = jt << 6;
        __syncthreads();

        // Commit prefetched K/V tiles
#pragma unroll
        for (int r = 0; r < 4; r++) {
            int fi = tid + r * 128;
            int row = fi >> 3, c4 = (fi & 7) << 2;
            *(uint4*)&Ks[row * ST + c4] = pk[r];
            *(uint4*)&Vt[row * ST + c4] = pv[r];
        }
        // Stage P slab (128 rows)
        const int rbase = 960 + j0 - i0;
#pragma unroll
        for (int r = 0; r < 8; r++) {
            int fi = tid + r * 128;
            int row = fi >> 3, hc = (fi & 7) << 3;
            int prow = rbase + row;
            prow = prow > 2046 ? 2046 : prow;
            *(uint4*)&Ps[row * ST + ((fi & 7) << 2)] =
                *(const uint4*)(pp + ((size_t)h * 2047 + prow) * 64 + hc);
        }
        __syncthreads();

        // Prefetch next j-tile's K/V
        if (jt + 1 < 16) {
            const int jn = (jt + 1) << 6;
#pragma unroll
            for (int r = 0; r < 4; r++) {
                int fi = tid + r * 128;
                int row = fi >> 3, hc = (fi & 7) << 3;
                pk[r] = *(const uint4*)(kk + ((size_t)bh * 1024 + jn + row) * 64 + hc);
                pv[r] = *(const uint4*)(vt + ((size_t)bh * 64 + row) * 1024 + jn + hc);
            }
        }

        // E = Qv @ P_slab^T over band n-tiles; compacted f32 into Cp.
#pragma unroll
        for (int nt = 0; nt < 16; nt++) {
            if (nt * 8 + 7 < lo || nt * 8 > hi) continue;
            float e[4] = {0.f, 0.f, 0.f, 0.f};
#pragma unroll
            for (int ks = 0; ks < 4; ks++) {
                int rb = nt * 8 + gid, cb = ks * 8 + tig;
                mma16(e, qva[ks], Ps[rb * ST + cb], Ps[rb * ST + cb + 4]);
            }
            int er = w * 16 + gid, ec = nt * 8 + 2 * tig;
#pragma unroll
            for (int hh = 0; hh < 2; hh++) {
#pragma unroll
                for (int cc = 0; cc < 2; cc++) {
                    int row = er + 8 * hh;
                    int col = ec + cc - 63 + row;
                    if (col >= 0 && col < 64)
                        Cp[row * CST + col] = e[2 * hh + cc];
                }
            }
        }
        __syncwarp();

        // S1 = Qu @ K^T
        float sC[8][4];
#pragma unroll
        for (int nt = 0; nt < 8; nt++)
#pragma unroll
            for (int i = 0; i < 4; i++) sC[nt][i] = 0.f;
#pragma unroll
        for (int ks = 0; ks < 4; ks++) {
#pragma unroll
            for (int nt = 0; nt < 8; nt++) {
                int rb = nt * 8 + gid, cb = ks * 8 + tig;
                mma16(sC[nt], qua[ks], Ks[rb * ST + cb], Ks[rb * ST + cb + 4]);
            }
        }

        // Online softmax; exp(S) packed fp16 into Ep
#pragma unroll
        for (int hh = 0; hh < 2; hh++) {
            int qrow = w * 16 + gid + 8 * hh;
            float sv[16];
            float mx = -1e30f;
#pragma unroll
            for (int nt = 0; nt < 8; nt++) {
#pragma unroll
                for (int cc = 0; cc < 2; cc++) {
                    int jl = nt * 8 + 2 * tig + cc;
                    float s = sC[nt][2 * hh + cc] + Cp[qrow * CST + jl];
                    sv[nt * 2 + cc] = s;
                    mx = fmaxf(mx, s);
                }
            }
            mx = fmaxf(mx, __shfl_xor_sync(0xffffffffu, mx, 1));
            mx = fmaxf(mx, __shfl_xor_sync(0xffffffffu, mx, 2));
            float mn = fmaxf(m_i[hh], mx);
            float al = __expf(m_i[hh] - mn);
            float rs = 0.f;
#pragma unroll
            for (int nt = 0; nt < 8; nt++) {
                float p0 = __expf(sv[nt * 2] - mn);
                float p1 = __expf(sv[nt * 2 + 1] - mn);
                rs += p0 + p1;
                Ep[qrow * ST + nt * 4 + tig] = pack2(p0, p1);
            }
            rs += __shfl_xor_sync(0xffffffffu, rs, 1);
            rs += __shfl_xor_sync(0xffffffffu, rs, 2);
            l_i[hh] = l_i[hh] * al + rs;
            m_i[hh] = mn;
#pragma unroll
            for (int nt = 0; nt < 8; nt++) {
                oC[nt][2 * hh] *= al;
                oC[nt][2 * hh + 1] *= al;
            }
        }
        __syncwarp();

        // O += exp(S) @ V
#pragma unroll
        for (int ks = 0; ks < 4; ks++) {
            uint32_t a[4];
            int rb = w * 16 + gid, cb = ks * 8 + tig;
            a[0] = Ep[rb * ST + cb];
            a[1] = Ep[(rb + 8) * ST + cb];
            a[2] = Ep[rb * ST + cb + 4];
            a[3] = Ep[(rb + 8) * ST + cb + 4];
#pragma unroll
            for (int nt = 0; nt < 8; nt++) {
                int nb = nt * 8 + gid;
                uint32_t b0 = Vt[nb * ST + cb];
                uint32_t b1 = Vt[nb * ST + cb + 4];
                mma16(oC[nt], a, b0, b1);
            }
        }
    }

    // Write normalized output as fp16 pairs: att[b*1024+t][h*64+d]
#pragma unroll
    for (int hh = 0; hh < 2; hh++) {
        int t = i0 + w * 16 + gid + 8 * hh;
        float inv = 1.f / l_i[hh];
#pragma unroll
        for (int nt = 0; nt < 8; nt++) {
            int d = nt * 8 + 2 * tig;
            size_t i32 = (((size_t)b * 1024 + t) * 512 + h * 64 + d) >> 1;
            ((uint32_t*)att)[i32] =
                pack2(oC[nt][2 * hh] * inv, oC[nt][2 * hh + 1] * inv);
        }
    }
}

// ---------------------------------------------------------------------------
extern "C" void kernel_launch(void* const* d_in, const int* in_sizes, int n_in,
                              void* d_out, int out_size)
{
    const float* query = (const float*)d_in[0];
    const float* key   = (const float*)d_in[1];
    const float* value = (const float*)d_in[2];
    const float* pos   = (const float*)d_in[3];
    const float* Wq    = (const float*)d_in[4];
    const float* bq    = (const float*)d_in[5];
    const float* Wk    = (const float*)d_in[6];
    const float* bk    = (const float*)d_in[7];
    const float* Wv    = (const float*)d_in[8];
    const float* bv_   = (const float*)d_in[9];
    const float* Wp    = (const float*)d_in[10];
    const float* Wo    = (const float*)d_in[11];
    const float* bo    = (const float*)d_in[12];
    const float* pbu   = (const float*)d_in[13];
    const float* pbv   = (const float*)d_in[14];

    __half *qu_p, *qv_p, *k_p, *vt_p, *p_p, *att_p;
    cudaGetSymbolAddress((void**)&qu_p,  g_qu16);
    cudaGetSymbolAddress((void**)&qv_p,  g_qv16);
    cudaGetSymbolAddress((void**)&k_p,   g_k16);
    cudaGetSymbolAddress((void**)&vt_p,  g_vt16);
    cudaGetSymbolAddress((void**)&p_p,   g_p16);
    cudaGetSymbolAddress((void**)&att_p, g_att16);

    cudaFuncSetAttribute(attn_mma,
                         cudaFuncAttributeMaxDynamicSharedMemorySize,
                         ATT_SMEM_BYTES);

    gemm_fused<<<dim3(8, 64, 4), 256>>>(
        query, key, value, pos, Wq, Wk, Wv, Wp,
        bq, bk, bv_, pbu, pbv,
        qu_p, qv_p, k_p, vt_p, p_p);

    attn_mma<<<dim3(16, 64), dim3(128), ATT_SMEM_BYTES>>>(qu_p, qv_p, k_p, vt_p,
                                                          p_p, att_p);

    gemm_out<<<dim3(8, 64), 256>>>(att_p, Wo, bo, (float*)d_out);
}

// round 16
// speedup vs baseline: 1.9244x; 1.0492x over previous
#include <cuda_runtime.h>
#include <cuda_fp16.h>
#include <cstdint>

// Problem constants: B=8, T=1024, F=512, H=8, D=64, P=2047
__device__ __half g_qu16[8 * 8 * 1024 * 64];  // [B,H,T,D] (q+bu)*scale, fp16
__device__ __half g_qv16[8 * 8 * 1024 * 64];  // [B,H,T,D] (q+bv)*scale, fp16
__device__ __half g_k16 [8 * 8 * 1024 * 64];  // [B,H,T,D] fp16
__device__ __half g_vt16[8 * 8 * 64 * 1024];  // [B,H,D,T] fp16 (transposed!)
__device__ __half g_p16 [8 * 2047 * 64];      // [H,P,D] fp16
__device__ __half g_att16[8 * 1024 * 512];    // [B*T, F] fp16

// fp16 mma (f32 accumulate)
__device__ __forceinline__ void mma16(float c[4], const uint32_t a[4],
                                      uint32_t b0, uint32_t b1) {
    asm volatile(
        "mma.sync.aligned.m16n8k16.row.col.f32.f16.f16.f32 "
        "{%0,%1,%2,%3},{%4,%5,%6,%7},{%8,%9},{%0,%1,%2,%3};"
        : "+f"(c[0]), "+f"(c[1]), "+f"(c[2]), "+f"(c[3])
        : "r"(a[0]), "r"(a[1]), "r"(a[2]), "r"(a[3]), "r"(b0), "r"(b1));
}

// Pack two fp32 into fp16x2 (lo -> low half), round-to-nearest.
__device__ __forceinline__ uint32_t pack2(float lo, float hi) {
    uint32_t u;
    asm("cvt.rn.f16x2.f32 %0, %1, %2;" : "=r"(u) : "f"(hi), "f"(lo));
    return u;
}

// Convert 8 consecutive fp32 at src into one uint4 of 8 fp16.
__device__ __forceinline__ uint4 cvt8(const float* src) {
    float4 f0 = *(const float4*)src;
    float4 f1 = *(const float4*)(src + 4);
    uint4 o;
    o.x = pack2(f0.x, f0.y); o.y = pack2(f0.z, f0.w);
    o.z = pack2(f1.x, f1.y); o.w = pack2(f1.z, f1.w);
    return o;
}

// ---------------------------------------------------------------------------
// FP16 NT GEMM core: C[m,n] = sum_k A[m,k]*W[n,k], K=N=512, fp32 accum.
// Block tile 128x64, BK=64 (8 iters), register-prefetch double buffering.
// 256 threads = 8 warps (4m x 2n), warp tile 32x32, m16n8k16.
// A source is fp32 (converted on stage) or fp16 (direct).  (proven R15)
// ---------------------------------------------------------------------------
#define HST 36   // u32 stride per row (32 used = 64 halves)

template <bool A_IS_HALF>
__device__ __forceinline__ void hgemm_core(
    const void* __restrict__ Asrc, const float* __restrict__ W, int M,
    int m0, int n0, uint32_t* As, uint32_t* Ws, float acc[2][4][4])
{
    const int tid = threadIdx.x;
    const int warp = tid >> 5, lane = tid & 31;
    const int gid = lane >> 2, tig = lane & 3;
    const int wm = warp & 3, wn = warp >> 2;

#pragma unroll
    for (int mt = 0; mt < 2; mt++)
#pragma unroll
        for (int nt = 0; nt < 4; nt++)
#pragma unroll
            for (int i = 0; i < 4; i++) acc[mt][nt][i] = 0.f;

    uint4 pa[4], pw[2];
    const uint4 z4 = make_uint4(0u, 0u, 0u, 0u);

    auto ldA = [&](int k0, int r) -> uint4 {
        int ch = tid + r * 256;
        int row = ch >> 3, h8 = (ch & 7) << 3;
        int gm = m0 + row;
        if (gm >= M) return z4;
        if (A_IS_HALF)
            return *(const uint4*)((const __half*)Asrc + (size_t)gm * 512 + k0 + h8);
        else
            return cvt8((const float*)Asrc + (size_t)gm * 512 + k0 + h8);
    };
    auto ldW = [&](int k0, int r) -> uint4 {
        int ch = tid + r * 256;
        int row = ch >> 3, h8 = (ch & 7) << 3;
        return cvt8(W + (size_t)(n0 + row) * 512 + k0 + h8);
    };

#pragma unroll
    for (int r = 0; r < 4; r++) pa[r] = ldA(0, r);
#pragma unroll
    for (int r = 0; r < 2; r++) pw[r] = ldW(0, r);

    for (int it = 0; it < 8; it++) {
#pragma unroll
        for (int r = 0; r < 4; r++) {
            int ch = tid + r * 256;
            int row = ch >> 3, c4 = (ch & 7) << 2;
            *(uint4*)&As[row * HST + c4] = pa[r];
        }
#pragma unroll
        for (int r = 0; r < 2; r++) {
            int ch = tid + r * 256;
            int row = ch >> 3, c4 = (ch & 7) << 2;
            *(uint4*)&Ws[row * HST + c4] = pw[r];
        }
        __syncthreads();

        if (it + 1 < 8) {
            int k0 = (it + 1) * 64;
#pragma unroll
            for (int r = 0; r < 4; r++) pa[r] = ldA(k0, r);
#pragma unroll
            for (int r = 0; r < 2; r++) pw[r] = ldW(k0, r);
        }

#pragma unroll
        for (int ks = 0; ks < 4; ks++) {
            uint32_t a[2][4];
#pragma unroll
            for (int mt = 0; mt < 2; mt++) {
                int rb = wm * 32 + mt * 16 + gid, cb = ks * 8 + tig;
                a[mt][0] = As[rb * HST + cb];
                a[mt][1] = As[(rb + 8) * HST + cb];
                a[mt][2] = As[rb * HST + cb + 4];
                a[mt][3] = As[(rb + 8) * HST + cb + 4];
            }
#pragma unroll
            for (int nt = 0; nt < 4; nt++) {
                int nb = wn * 32 + nt * 8 + gid;
                uint32_t b0 = Ws[nb * HST + ks * 8 + tig];
                uint32_t b1 = Ws[nb * HST + ks * 8 + tig + 4];
                mma16(acc[0][nt], a[0], b0, b1);
                mma16(acc[1][nt], a[1], b0, b1);
            }
        }
        __syncthreads();
    }
}

// Fused Q/K/V/P projection GEMM; fp16 pair-packed outputs (V transposed).
__global__ __launch_bounds__(256) void gemm_fused(
    const float* __restrict__ query, const float* __restrict__ key,
    const float* __restrict__ value, const float* __restrict__ pos,
    const float* __restrict__ Wq, const float* __restrict__ Wk,
    const float* __restrict__ Wv, const float* __restrict__ Wp,
    const float* __restrict__ bq, const float* __restrict__ bk,
    const float* __restrict__ bvb, const float* __restrict__ bu,
    const float* __restrict__ bvv,
    __half* __restrict__ o_qu, __half* __restrict__ o_qv,
    __half* __restrict__ o_k, __half* __restrict__ o_v,
    __half* __restrict__ o_p)
{
    __shared__ __align__(16) uint32_t As[128 * HST];
    __shared__ __align__(16) uint32_t Ws[64 * HST];

    const int z = blockIdx.z;
    const float *A, *W;
    int M;
    if (z == 0)      { A = query; W = Wq; M = 8192; }
    else if (z == 1) { A = key;   W = Wk; M = 8192; }
    else if (z == 2) { A = value; W = Wv; M = 8192; }
    else             { A = pos;   W = Wp; M = 2047; }

    const int m0 = blockIdx.y * 128, n0 = blockIdx.x * 64;
    if (m0 >= M) return;

    float acc[2][4][4];
    hgemm_core<false>(A, W, M, m0, n0, As, Ws, acc);

    const int tid = threadIdx.x;
    const int warp = tid >> 5, lane = tid & 31;
    const int gid = lane >> 2, tig = lane & 3;
    const int wm = warp & 3, wn = warp >> 2;
    const float scale = 0.125f;

#pragma unroll
    for (int mt = 0; mt < 2; mt++) {
#pragma unroll
        for (int hh = 0; hh < 2; hh++) {
            int m = m0 + wm * 32 + mt * 16 + gid + 8 * hh;
            if (m >= M) continue;
#pragma unroll
            for (int nt = 0; nt < 4; nt++) {
                int n = n0 + wn * 32 + nt * 8 + 2 * tig;   // even, pair (n,n+1)
                float v0 = acc[mt][nt][2 * hh];
                float v1 = acc[mt][nt][2 * hh + 1];
                if (z == 0) {
                    int b = m >> 10, t = m & 1023, h = n >> 6, d = n & 63;
                    float b0 = v0 + bq[n], b1 = v1 + bq[n + 1];
                    size_t i32 = ((((size_t)(b * 8 + h) << 10) + t) << 5) + (d >> 1);
                    ((uint32_t*)o_qu)[i32] =
                        pack2((b0 + bu[n]) * scale, (b1 + bu[n + 1]) * scale);
                    ((uint32_t*)o_qv)[i32] =
                        pack2((b0 + bvv[n]) * scale, (b1 + bvv[n + 1]) * scale);
                } else if (z == 1) {
                    int b = m >> 10, t = m & 1023, h = n >> 6, d = n & 63;
                    size_t i32 = ((((size_t)(b * 8 + h) << 10) + t) << 5) + (d >> 1);
                    ((uint32_t*)o_k)[i32] = pack2(v0 + bk[n], v1 + bk[n + 1]);
                } else if (z == 2) {
                    int b = m >> 10, t = m & 1023, h = n >> 6, d = n & 63;
                    // transposed: [bh][d][t]
                    o_v[((size_t)(b * 8 + h) * 64 + d) * 1024 + t] =
                        __float2half_rn(v0 + bvb[n]);
                    o_v[((size_t)(b * 8 + h) * 64 + d + 1) * 1024 + t] =
                        __float2half_rn(v1 + bvb[n + 1]);
                } else {
                    int h = n >> 6, d = n & 63;
                    size_t i32 = (((size_t)h * 2047 + m) << 5) + (d >> 1);
                    ((uint32_t*)o_p)[i32] = pack2(v0, v1);
                }
            }
        }
    }
}

// Output projection GEMM: d_out = att16 @ Wo^T + bo (A fp16, W converted).
__global__ __launch_bounds__(256) void gemm_out(
    const __half* __restrict__ A16, const float* __restrict__ W,
    const float* __restrict__ bias, float* __restrict__ out)
{
    __shared__ __align__(16) uint32_t As[128 * HST];
    __shared__ __align__(16) uint32_t Ws[64 * HST];

    const int m0 = blockIdx.y * 128, n0 = blockIdx.x * 64;
    float acc[2][4][4];
    hgemm_core<true>(A16, W, 8192, m0, n0, As, Ws, acc);

    const int tid = threadIdx.x;
    const int warp = tid >> 5, lane = tid & 31;
    const int gid = lane >> 2, tig = lane & 3;
    const int wm = warp & 3, wn = warp >> 2;

#pragma unroll
    for (int mt = 0; mt < 2; mt++)
#pragma unroll
        for (int hh = 0; hh < 2; hh++) {
            int m = m0 + wm * 32 + mt * 16 + gid + 8 * hh;
#pragma unroll
            for (int nt = 0; nt < 4; nt++)
#pragma unroll
                for (int cc = 0; cc < 2; cc++) {
                    int n = n0 + wn * 32 + nt * 8 + 2 * tig + cc;
                    out[(size_t)m * 512 + n] = acc[mt][nt][2 * hh + cc] + bias[n];
                }
        }
}

// ---------------------------------------------------------------------------
// FP16 flash attention with relative positions.
// exp(S) now lives ONLY in registers: thread (gid,tig) computes exactly the
// PV A-fragment elements (qrow=w16+gid+8hh, j=8nt+2tig+{0,1}), packed as
// aE[ks][(nt&1)*2+hh].  No Ep buffer, no smem roundtrip.
// smem 53KB -> 4 CTAs/SM (16 warps).  K/V staged synchronously (occupancy
// replaces register prefetch for latency hiding).
// ---------------------------------------------------------------------------
#define ST 36     // u32 stride of fp16 tiles
#define CST 68    // f32 stride of Cp band
#define ATT_SMEM_U32 (256 * ST + 64 * CST)
#define ATT_SMEM_BYTES (ATT_SMEM_U32 * 4)

__global__ __launch_bounds__(128, 4) void attn_mma(
    const __half* __restrict__ qu, const __half* __restrict__ qv,
    const __half* __restrict__ kk, const __half* __restrict__ vt,
    const __half* __restrict__ pp, __half* __restrict__ att)
{
    extern __shared__ __align__(16) uint32_t sh[];
    uint32_t* Ks = sh;                    // Qu staging, then K  (64 rows)
    uint32_t* Vt = sh + 64 * ST;          // Qv staging, then V^T (64 rows=d)
    uint32_t* Ps = sh + 2 * 64 * ST;      // P slab (128 rows)
    float*    Cp = (float*)(sh + 4 * 64 * ST);   // bias band f32 (64 x CST)

    const int tid = threadIdx.x;
    const int w = tid >> 5, lane = tid & 31;
    const int gid = lane >> 2, tig = lane & 3;
    const int i0 = blockIdx.x << 6;
    const int bh = blockIdx.y;
    const int h = bh & 7, b = bh >> 3;

    // Stage Qu -> Ks area, Qv -> Vt area
#pragma unroll
    for (int r = 0; r < 4; r++) {
        int fi = tid + r * 128;
        int row = fi >> 3, hc = (fi & 7) << 3;
        size_t g = ((size_t)bh * 1024 + i0 + row) * 64 + hc;
        *(uint4*)&Ks[row * ST + ((fi & 7) << 2)] = *(const uint4*)(qu + g);
        *(uint4*)&Vt[row * ST + ((fi & 7) << 2)] = *(const uint4*)(qv + g);
    }
    __syncthreads();

    uint32_t qua[4][4], qva[4][4];
#pragma unroll
    for (int ks = 0; ks < 4; ks++) {
        int rb = w * 16 + gid, cb = ks * 8 + tig;
        qua[ks][0] = Ks[rb * ST + cb];
        qua[ks][1] = Ks[(rb + 8) * ST + cb];
        qua[ks][2] = Ks[rb * ST + cb + 4];
        qua[ks][3] = Ks[(rb + 8) * ST + cb + 4];
        qva[ks][0] = Vt[rb * ST + cb];
        qva[ks][1] = Vt[(rb + 8) * ST + cb];
        qva[ks][2] = Vt[rb * ST + cb + 4];
        qva[ks][3] = Vt[(rb + 8) * ST + cb + 4];
    }

    float m_i[2] = {-1e30f, -1e30f}, l_i[2] = {0.f, 0.f};
    float oC[8][4];
#pragma unroll
    for (int nt = 0; nt < 8; nt++)
#pragma unroll
        for (int i = 0; i < 4; i++) oC[nt][i] = 0.f;

    // E band window for this warp's 16 rows: slab cols [48-16w, 126-16w]
    const int lo = 48 - w * 16, hi = 126 - w * 16;

    for (int jt = 0; jt < 16; jt++) {
        const int j0 = jt << 6;
        __syncthreads();   // prior iteration (and Q staging) done with smem

        // Stage K tile and V^T tile (synchronous; occupancy hides latency)
#pragma unroll
        for (int r = 0; r < 4; r++) {
            int fi = tid + r * 128;
            int row = fi >> 3, hc = (fi & 7) << 3;
            int c4 = (fi & 7) << 2;
            *(uint4*)&Ks[row * ST + c4] =
                *(const uint4*)(kk + ((size_t)bh * 1024 + j0 + row) * 64 + hc);
            *(uint4*)&Vt[row * ST + c4] =
                *(const uint4*)(vt + ((size_t)bh * 64 + row) * 1024 + j0 + hc);
        }
        // Stage P slab (128 rows)
        const int rbase = 960 + j0 - i0;
#pragma unroll
        for (int r = 0; r < 8; r++) {
            int fi = tid + r * 128;
            int row = fi >> 3, hc = (fi & 7) << 3;
            int prow = rbase + row;
            prow = prow > 2046 ? 2046 : prow;
            *(uint4*)&Ps[row * ST + ((fi & 7) << 2)] =
                *(const uint4*)(pp + ((size_t)h * 2047 + prow) * 64 + hc);
        }
        __syncthreads();

        // E = Qv @ P_slab^T over band n-tiles; compacted f32 into Cp.
#pragma unroll
        for (int nt = 0; nt < 16; nt++) {
            if (nt * 8 + 7 < lo || nt * 8 > hi) continue;
            float e[4] = {0.f, 0.f, 0.f, 0.f};
#pragma unroll
            for (int ks = 0; ks < 4; ks++) {
                int rb = nt * 8 + gid, cb = ks * 8 + tig;
                mma16(e, qva[ks], Ps[rb * ST + cb], Ps[rb * ST + cb + 4]);
            }
            int er = w * 16 + gid, ec = nt * 8 + 2 * tig;
#pragma unroll
            for (int hh = 0; hh < 2; hh++) {
#pragma unroll
                for (int cc = 0; cc < 2; cc++) {
                    int row = er + 8 * hh;
                    int col = ec + cc - 63 + row;
                    if (col >= 0 && col < 64)
                        Cp[row * CST + col] = e[2 * hh + cc];
                }
            }
        }
        __syncwarp();   // Cp rows warp-private; cross-lane visibility

        // S1 = Qu @ K^T
        float sC[8][4];
#pragma unroll
        for (int nt = 0; nt < 8; nt++)
#pragma unroll
            for (int i = 0; i < 4; i++) sC[nt][i] = 0.f;
#pragma unroll
        for (int ks = 0; ks < 4; ks++) {
#pragma unroll
            for (int nt = 0; nt < 8; nt++) {
                int rb = nt * 8 + gid, cb = ks * 8 + tig;
                mma16(sC[nt], qua[ks], Ks[rb * ST + cb], Ks[rb * ST + cb + 4]);
            }
        }

        // Online softmax; exp(S) packed straight into PV A-fragments (regs)
        uint32_t aE[4][4];
#pragma unroll
        for (int hh = 0; hh < 2; hh++) {
            int qrow = w * 16 + gid + 8 * hh;
            float sv[16];
            float mx = -1e30f;
#pragma unroll
            for (int nt = 0; nt < 8; nt++) {
#pragma unroll
                for (int cc = 0; cc < 2; cc++) {
                    int jl = nt * 8 + 2 * tig + cc;
                    float s = sC[nt][2 * hh + cc] + Cp[qrow * CST + jl];
                    sv[nt * 2 + cc] = s;
                    mx = fmaxf(mx, s);
                }
            }
            mx = fmaxf(mx, __shfl_xor_sync(0xffffffffu, mx, 1));
            mx = fmaxf(mx, __shfl_xor_sync(0xffffffffu, mx, 2));
            float mn = fmaxf(m_i[hh], mx);
            float al = __expf(m_i[hh] - mn);
            float rs = 0.f;
#pragma unroll
            for (int nt = 0; nt < 8; nt++) {
                float p0 = __expf(sv[nt * 2] - mn);
                float p1 = __expf(sv[nt * 2 + 1] - mn);
                rs += p0 + p1;
                aE[nt >> 1][((nt & 1) << 1) | hh] = pack2(p0, p1);
            }
            rs += __shfl_xor_sync(0xffffffffu, rs, 1);
            rs += __shfl_xor_sync(0xffffffffu, rs, 2);
            l_i[hh] = l_i[hh] * al + rs;
            m_i[hh] = mn;
#pragma unroll
            for (int nt = 0; nt < 8; nt++) {
                oC[nt][2 * hh] *= al;
                oC[nt][2 * hh + 1] *= al;
            }
        }

        // O += exp(S) @ V   (A fragments already in registers)
#pragma unroll
        for (int ks = 0; ks < 4; ks++) {
            int cb = ks * 8 + tig;
#pragma unroll
            for (int nt = 0; nt < 8; nt++) {
                int nb = nt * 8 + gid;
                uint32_t b0 = Vt[nb * ST + cb];
                uint32_t b1 = Vt[nb * ST + cb + 4];
                mma16(oC[nt], aE[ks], b0, b1);
            }
        }
    }

    // Write normalized output as fp16 pairs: att[b*1024+t][h*64+d]
#pragma unroll
    for (int hh = 0; hh < 2; hh++) {
        int t = i0 + w * 16 + gid + 8 * hh;
        float inv = 1.f / l_i[hh];
#pragma unroll
        for (int nt = 0; nt < 8; nt++) {
            int d = nt * 8 + 2 * tig;
            size_t i32 = (((size_t)b * 1024 + t) * 512 + h * 64 + d) >> 1;
            ((uint32_t*)att)[i32] =
                pack2(oC[nt][2 * hh] * inv, oC[nt][2 * hh + 1] * inv);
        }
    }
}

// ---------------------------------------------------------------------------
extern "C" void kernel_launch(void* const* d_in, const int* in_sizes, int n_in,
                              void* d_out, int out_size)
{
    const float* query = (const float*)d_in[0];
    const float* key   = (const float*)d_in[1];
    const float* value = (const float*)d_in[2];
    const float* pos   = (const float*)d_in[3];
    const float* Wq    = (const float*)d_in[4];
    const float* bq    = (const float*)d_in[5];
    const float* Wk    = (const float*)d_in[6];
    const float* bk    = (const float*)d_in[7];
    const float* Wv    = (const float*)d_in[8];
    const float* bv_   = (const float*)d_in[9];
    const float* Wp    = (const float*)d_in[10];
    const float* Wo    = (const float*)d_in[11];
    const float* bo    = (const float*)d_in[12];
    const float* pbu   = (const float*)d_in[13];
    const float* pbv   = (const float*)d_in[14];

    __half *qu_p, *qv_p, *k_p, *vt_p, *p_p, *att_p;
    cudaGetSymbolAddress((void**)&qu_p,  g_qu16);
    cudaGetSymbolAddress((void**)&qv_p,  g_qv16);
    cudaGetSymbolAddress((void**)&k_p,   g_k16);
    cudaGetSymbolAddress((void**)&vt_p,  g_vt16);
    cudaGetSymbolAddress((void**)&p_p,   g_p16);
    cudaGetSymbolAddress((void**)&att_p, g_att16);

    cudaFuncSetAttribute(attn_mma,
                         cudaFuncAttributeMaxDynamicSharedMemorySize,
                         ATT_SMEM_BYTES);

    gemm_fused<<<dim3(8, 64, 4), 256>>>(
        query, key, value, pos, Wq, Wk, Wv, Wp,
        bq, bk, bv_, pbu, pbv,
        qu_p, qv_p, k_p, vt_p, p_p);

    attn_mma<<<dim3(16, 64), dim3(128), ATT_SMEM_BYTES>>>(qu_p, qv_p, k_p, vt_p,
                                                          p_p, att_p);

    gemm_out<<<dim3(8, 64), 256>>>(att_p, Wo, bo, (float*)d_out);
}

// round 17
// speedup vs baseline: 2.0938x; 1.0880x over previous
#include <cuda_runtime.h>
#include <cuda_fp16.h>
#include <cstdint>

// Problem constants: B=8, T=1024, F=512, H=8, D=64, P=2047
__device__ __half g_qu16[8 * 8 * 1024 * 64];  // [B,H,T,D] (q+bu)*scale, fp16
__device__ __half g_qv16[8 * 8 * 1024 * 64];  // [B,H,T,D] (q+bv)*scale, fp16
__device__ __half g_k16 [8 * 8 * 1024 * 64];  // [B,H,T,D] fp16
__device__ __half g_vt16[8 * 8 * 64 * 1024];  // [B,H,D,T] fp16 (transposed!)
__device__ __half g_p16 [8 * 2047 * 64];      // [H,P,D] fp16
__device__ __half g_att16[8 * 1024 * 512];    // [B*T, F] fp16

// fp16 mma (f32 accumulate)
__device__ __forceinline__ void mma16(float c[4], const uint32_t a[4],
                                      uint32_t b0, uint32_t b1) {
    asm volatile(
        "mma.sync.aligned.m16n8k16.row.col.f32.f16.f16.f32 "
        "{%0,%1,%2,%3},{%4,%5,%6,%7},{%8,%9},{%0,%1,%2,%3};"
        : "+f"(c[0]), "+f"(c[1]), "+f"(c[2]), "+f"(c[3])
        : "r"(a[0]), "r"(a[1]), "r"(a[2]), "r"(a[3]), "r"(b0), "r"(b1));
}

// ldmatrix x4: 4 8x8 b16 tiles; each lane supplies one row address.
__device__ __forceinline__ void ldsm4(uint32_t r[4], uint32_t a) {
    asm volatile(
        "ldmatrix.sync.aligned.m8n8.x4.shared.b16 {%0,%1,%2,%3}, [%4];"
        : "=r"(r[0]), "=r"(r[1]), "=r"(r[2]), "=r"(r[3]) : "r"(a));
}

__device__ __forceinline__ uint32_t s2u(const void* p) {
    return (uint32_t)__cvta_generic_to_shared(p);
}

// Pack two fp32 into fp16x2 (lo -> low half), round-to-nearest.
__device__ __forceinline__ uint32_t pack2(float lo, float hi) {
    uint32_t u;
    asm("cvt.rn.f16x2.f32 %0, %1, %2;" : "=r"(u) : "f"(hi), "f"(lo));
    return u;
}

// Convert 8 consecutive fp32 at src into one uint4 of 8 fp16.
__device__ __forceinline__ uint4 cvt8(const float* src) {
    float4 f0 = *(const float4*)src;
    float4 f1 = *(const float4*)(src + 4);
    uint4 o;
    o.x = pack2(f0.x, f0.y); o.y = pack2(f0.z, f0.w);
    o.z = pack2(f1.x, f1.y); o.w = pack2(f1.z, f1.w);
    return o;
}

// ---------------------------------------------------------------------------
// FP16 NT GEMM core: C[m,n] = sum_k A[m,k]*W[n,k], K=N=512, fp32 accum.
// Block tile 128x64, BK=64 (8 iters), register-prefetch double buffering.
// 256 threads = 8 warps (4m x 2n), warp tile 32x32, m16n8k16.
// Fragments loaded via ldmatrix.x4 (A: 16x16 per LDSM; B: 2 n-tiles per LDSM)
// ---------------------------------------------------------------------------
#define HST 36            // u32 stride per row (32 used = 64 halves)
#define ROWB (HST * 4)    // 144 bytes per row

template <bool A_IS_HALF>
__device__ __forceinline__ void hgemm_core(
    const void* __restrict__ Asrc, const float* __restrict__ W, int M,
    int m0, int n0, uint32_t* As, uint32_t* Ws, float acc[2][4][4])
{
    const int tid = threadIdx.x;
    const int warp = tid >> 5, lane = tid & 31;
    const int wm = warp & 3, wn = warp >> 2;

#pragma unroll
    for (int mt = 0; mt < 2; mt++)
#pragma unroll
        for (int nt = 0; nt < 4; nt++)
#pragma unroll
            for (int i = 0; i < 4; i++) acc[mt][nt][i] = 0.f;

    uint4 pa[4], pw[2];
    const uint4 z4 = make_uint4(0u, 0u, 0u, 0u);

    auto ldA = [&](int k0, int r) -> uint4 {
        int ch = tid + r * 256;
        int row = ch >> 3, h8 = (ch & 7) << 3;
        int gm = m0 + row;
        if (gm >= M) return z4;
        if (A_IS_HALF)
            return *(const uint4*)((const __half*)Asrc + (size_t)gm * 512 + k0 + h8);
        else
            return cvt8((const float*)Asrc + (size_t)gm * 512 + k0 + h8);
    };
    auto ldW = [&](int k0, int r) -> uint4 {
        int ch = tid + r * 256;
        int row = ch >> 3, h8 = (ch & 7) << 3;
        return cvt8(W + (size_t)(n0 + row) * 512 + k0 + h8);
    };

#pragma unroll
    for (int r = 0; r < 4; r++) pa[r] = ldA(0, r);
#pragma unroll
    for (int r = 0; r < 2; r++) pw[r] = ldW(0, r);

    // ldmatrix base addresses (per-lane row addressing)
    const uint32_t aB = s2u(As) +
        (uint32_t)(wm * 32 + (lane & 15)) * ROWB + ((lane >> 4) << 4);
    const uint32_t wB = s2u(Ws) +
        (uint32_t)(wn * 32 + ((lane >> 4) << 3) + (lane & 7)) * ROWB +
        (((lane >> 3) & 1) << 4);

    for (int it = 0; it < 8; it++) {
#pragma unroll
        for (int r = 0; r < 4; r++) {
            int ch = tid + r * 256;
            int row = ch >> 3, c4 = (ch & 7) << 2;
            *(uint4*)&As[row * HST + c4] = pa[r];
        }
#pragma unroll
        for (int r = 0; r < 2; r++) {
            int ch = tid + r * 256;
            int row = ch >> 3, c4 = (ch & 7) << 2;
            *(uint4*)&Ws[row * HST + c4] = pw[r];
        }
        __syncthreads();

        if (it + 1 < 8) {
            int k0 = (it + 1) * 64;
#pragma unroll
            for (int r = 0; r < 4; r++) pa[r] = ldA(k0, r);
#pragma unroll
            for (int r = 0; r < 2; r++) pw[r] = ldW(k0, r);
        }

#pragma unroll
        for (int ks = 0; ks < 4; ks++) {
            uint32_t a0[4], a1[4], b0[4], b1[4];
            ldsm4(a0, aB + ks * 32);
            ldsm4(a1, aB + 16 * ROWB + ks * 32);
            ldsm4(b0, wB + ks * 32);
            ldsm4(b1, wB + 16 * ROWB + ks * 32);
            mma16(acc[0][0], a0, b0[0], b0[1]);
            mma16(acc[0][1], a0, b0[2], b0[3]);
            mma16(acc[0][2], a0, b1[0], b1[1]);
            mma16(acc[0][3], a0, b1[2], b1[3]);
            mma16(acc[1][0], a1, b0[0], b0[1]);
            mma16(acc[1][1], a1, b0[2], b0[3]);
            mma16(acc[1][2], a1, b1[0], b1[1]);
            mma16(acc[1][3], a1, b1[2], b1[3]);
        }
        __syncthreads();
    }
}

// Fused Q/K/V/P projection GEMM; fp16 pair-packed outputs (V transposed).
__global__ __launch_bounds__(256) void gemm_fused(
    const float* __restrict__ query, const float* __restrict__ key,
    const float* __restrict__ value, const float* __restrict__ pos,
    const float* __restrict__ Wq, const float* __restrict__ Wk,
    const float* __restrict__ Wv, const float* __restrict__ Wp,
    const float* __restrict__ bq, const float* __restrict__ bk,
    const float* __restrict__ bvb, const float* __restrict__ bu,
    const float* __restrict__ bvv,
    __half* __restrict__ o_qu, __half* __restrict__ o_qv,
    __half* __restrict__ o_k, __half* __restrict__ o_v,
    __half* __restrict__ o_p)
{
    __shared__ __align__(16) uint32_t As[128 * HST];
    __shared__ __align__(16) uint32_t Ws[64 * HST];

    const int z = blockIdx.z;
    const float *A, *W;
    int M;
    if (z == 0)      { A = query; W = Wq; M = 8192; }
    else if (z == 1) { A = key;   W = Wk; M = 8192; }
    else if (z == 2) { A = value; W = Wv; M = 8192; }
    else             { A = pos;   W = Wp; M = 2047; }

    const int m0 = blockIdx.y * 128, n0 = blockIdx.x * 64;
    if (m0 >= M) return;

    float acc[2][4][4];
    hgemm_core<false>(A, W, M, m0, n0, As, Ws, acc);

    const int tid = threadIdx.x;
    const int warp = tid >> 5, lane = tid & 31;
    const int gid = lane >> 2, tig = lane & 3;
    const int wm = warp & 3, wn = warp >> 2;
    const float scale = 0.125f;

#pragma unroll
    for (int mt = 0; mt < 2; mt++) {
#pragma unroll
        for (int hh = 0; hh < 2; hh++) {
            int m = m0 + wm * 32 + mt * 16 + gid + 8 * hh;
            if (m >= M) continue;
#pragma unroll
            for (int nt = 0; nt < 4; nt++) {
                int n = n0 + wn * 32 + nt * 8 + 2 * tig;   // even, pair (n,n+1)
                float v0 = acc[mt][nt][2 * hh];
                float v1 = acc[mt][nt][2 * hh + 1];
                if (z == 0) {
                    int b = m >> 10, t = m & 1023, h = n >> 6, d = n & 63;
                    float b0 = v0 + bq[n], b1 = v1 + bq[n + 1];
                    size_t i32 = ((((size_t)(b * 8 + h) << 10) + t) << 5) + (d >> 1);
                    ((uint32_t*)o_qu)[i32] =
                        pack2((b0 + bu[n]) * scale, (b1 + bu[n + 1]) * scale);
                    ((uint32_t*)o_qv)[i32] =
                        pack2((b0 + bvv[n]) * scale, (b1 + bvv[n + 1]) * scale);
                } else if (z == 1) {
                    int b = m >> 10, t = m & 1023, h = n >> 6, d = n & 63;
                    size_t i32 = ((((size_t)(b * 8 + h) << 10) + t) << 5) + (d >> 1);
                    ((uint32_t*)o_k)[i32] = pack2(v0 + bk[n], v1 + bk[n + 1]);
                } else if (z == 2) {
                    int b = m >> 10, t = m & 1023, h = n >> 6, d = n & 63;
                    // transposed: [bh][d][t]
                    o_v[((size_t)(b * 8 + h) * 64 + d) * 1024 + t] =
                        __float2half_rn(v0 + bvb[n]);
                    o_v[((size_t)(b * 8 + h) * 64 + d + 1) * 1024 + t] =
                        __float2half_rn(v1 + bvb[n + 1]);
                } else {
                    int h = n >> 6, d = n & 63;
                    size_t i32 = (((size_t)h * 2047 + m) << 5) + (d >> 1);
                    ((uint32_t*)o_p)[i32] = pack2(v0, v1);
                }
            }
        }
    }
}

// Output projection GEMM: d_out = att16 @ Wo^T + bo (A fp16, W converted).
__global__ __launch_bounds__(256) void gemm_out(
    const __half* __restrict__ A16, const float* __restrict__ W,
    const float* __restrict__ bias, float* __restrict__ out)
{
    __shared__ __align__(16) uint32_t As[128 * HST];
    __shared__ __align__(16) uint32_t Ws[64 * HST];

    const int m0 = blockIdx.y * 128, n0 = blockIdx.x * 64;
    float acc[2][4][4];
    hgemm_core<true>(A16, W, 8192, m0, n0, As, Ws, acc);

    const int tid = threadIdx.x;
    const int warp = tid >> 5, lane = tid & 31;
    const int gid = lane >> 2, tig = lane & 3;
    const int wm = warp & 3, wn = warp >> 2;

#pragma unroll
    for (int mt = 0; mt < 2; mt++)
#pragma unroll
        for (int hh = 0; hh < 2; hh++) {
            int m = m0 + wm * 32 + mt * 16 + gid + 8 * hh;
#pragma unroll
            for (int nt = 0; nt < 4; nt++)
#pragma unroll
                for (int cc = 0; cc < 2; cc++) {
                    int n = n0 + wn * 32 + nt * 8 + 2 * tig + cc;
                    out[(size_t)m * 512 + n] = acc[mt][nt][2 * hh + cc] + bias[n];
                }
        }
}

// ---------------------------------------------------------------------------
// FP16 flash attention with relative positions.
// exp(S) in registers (PV A-fragments); all B operands via ldmatrix.x4.
// E band is always 10 n-tiles starting at even nt=6-2w -> 5 LDSM pairs.
// smem 53KB -> 4 CTAs/SM.
// ---------------------------------------------------------------------------
#define ST 36     // u32 stride of fp16 tiles
#define SROWB (ST * 4)
#define CST 68    // f32 stride of Cp band
#define ATT_SMEM_U32 (256 * ST + 64 * CST)
#define ATT_SMEM_BYTES (ATT_SMEM_U32 * 4)

__global__ __launch_bounds__(128, 4) void attn_mma(
    const __half* __restrict__ qu, const __half* __restrict__ qv,
    const __half* __restrict__ kk, const __half* __restrict__ vt,
    const __half* __restrict__ pp, __half* __restrict__ att)
{
    extern __shared__ __align__(16) uint32_t sh[];
    uint32_t* Ks = sh;                    // Qu staging, then K  (64 rows)
    uint32_t* Vt = sh + 64 * ST;          // Qv staging, then V^T (64 rows=d)
    uint32_t* Ps = sh + 2 * 64 * ST;      // P slab (128 rows)
    float*    Cp = (float*)(sh + 4 * 64 * ST);   // bias band f32 (64 x CST)

    const int tid = threadIdx.x;
    const int w = tid >> 5, lane = tid & 31;
    const int gid = lane >> 2, tig = lane & 3;
    const int i0 = blockIdx.x << 6;
    const int bh = blockIdx.y;
    const int h = bh & 7, b = bh >> 3;

    // Stage Qu -> Ks area, Qv -> Vt area
#pragma unroll
    for (int r = 0; r < 4; r++) {
        int fi = tid + r * 128;
        int row = fi >> 3, hc = (fi & 7) << 3;
        size_t g = ((size_t)bh * 1024 + i0 + row) * 64 + hc;
        *(uint4*)&Ks[row * ST + ((fi & 7) << 2)] = *(const uint4*)(qu + g);
        *(uint4*)&Vt[row * ST + ((fi & 7) << 2)] = *(const uint4*)(qv + g);
    }
    __syncthreads();

    uint32_t qua[4][4], qva[4][4];
#pragma unroll
    for (int ks = 0; ks < 4; ks++) {
        int rb = w * 16 + gid, cb = ks * 8 + tig;
        qua[ks][0] = Ks[rb * ST + cb];
        qua[ks][1] = Ks[(rb + 8) * ST + cb];
        qua[ks][2] = Ks[rb * ST + cb + 4];
        qua[ks][3] = Ks[(rb + 8) * ST + cb + 4];
        qva[ks][0] = Vt[rb * ST + cb];
        qva[ks][1] = Vt[(rb + 8) * ST + cb];
        qva[ks][2] = Vt[rb * ST + cb + 4];
        qva[ks][3] = Vt[(rb + 8) * ST + cb + 4];
    }

    float m_i[2] = {-1e30f, -1e30f}, l_i[2] = {0.f, 0.f};
    float oC[8][4];
#pragma unroll
    for (int nt = 0; nt < 8; nt++)
#pragma unroll
        for (int i = 0; i < 4; i++) oC[nt][i] = 0.f;

    // ldmatrix B-operand base addresses (n-tile pair addressing)
    const uint32_t brow = ((lane >> 4) << 3) + (lane & 7);
    const uint32_t bcol = ((lane >> 3) & 1) << 4;
    const uint32_t kB = s2u(Ks) + brow * SROWB + bcol;
    const uint32_t vB = s2u(Vt) + brow * SROWB + bcol;
    const uint32_t pB = s2u(Ps) + ((6 - 2 * w) * 8 + brow) * SROWB + bcol;

    for (int jt = 0; jt < 16; jt++) {
        const int j0 = jt << 6;
        __syncthreads();   // prior iteration (and Q staging) done with smem

        // Stage K tile and V^T tile
#pragma unroll
        for (int r = 0; r < 4; r++) {
            int fi = tid + r * 128;
            int row = fi >> 3, hc = (fi & 7) << 3;
            int c4 = (fi & 7) << 2;
            *(uint4*)&Ks[row * ST + c4] =
                *(const uint4*)(kk + ((size_t)bh * 1024 + j0 + row) * 64 + hc);
            *(uint4*)&Vt[row * ST + c4] =
                *(const uint4*)(vt + ((size_t)bh * 64 + row) * 1024 + j0 + hc);
        }
        // Stage P slab (128 rows)
        const int rbase = 960 + j0 - i0;
#pragma unroll
        for (int r = 0; r < 8; r++) {
            int fi = tid + r * 128;
            int row = fi >> 3, hc = (fi & 7) << 3;
            int prow = rbase + row;
            prow = prow > 2046 ? 2046 : prow;
            *(uint4*)&Ps[row * ST + ((fi & 7) << 2)] =
                *(const uint4*)(pp + ((size_t)h * 2047 + prow) * 64 + hc);
        }
        __syncthreads();

        // E = Qv @ P_slab^T over the 10-tile band (5 ldmatrix pairs)
#pragma unroll
        for (int p = 0; p < 5; p++) {
            float e0[4] = {0.f, 0.f, 0.f, 0.f};
            float e1[4] = {0.f, 0.f, 0.f, 0.f};
#pragma unroll
            for (int ks = 0; ks < 4; ks++) {
                uint32_t bb[4];
                ldsm4(bb, pB + p * (16 * SROWB) + ks * 32);
                mma16(e0, qva[ks], bb[0], bb[1]);
                mma16(e1, qva[ks], bb[2], bb[3]);
            }
            int er = w * 16 + gid;
#pragma unroll
            for (int half = 0; half < 2; half++) {
                const float* e = half ? e1 : e0;
                int nt = 6 - 2 * w + 2 * p + half;
                int ec = nt * 8 + 2 * tig;
#pragma unroll
                for (int hh = 0; hh < 2; hh++) {
#pragma unroll
                    for (int cc = 0; cc < 2; cc++) {
                        int row = er + 8 * hh;
                        int col = ec + cc - 63 + row;
                        if (col >= 0 && col < 64)
                            Cp[row * CST + col] = e[2 * hh + cc];
                    }
                }
            }
        }
        __syncwarp();   // Cp rows warp-private; cross-lane visibility

        // S1 = Qu @ K^T (ldmatrix pairs)
        float sC[8][4];
#pragma unroll
        for (int nt = 0; nt < 8; nt++)
#pragma unroll
            for (int i = 0; i < 4; i++) sC[nt][i] = 0.f;
#pragma unroll
        for (int ks = 0; ks < 4; ks++) {
#pragma unroll
            for (int np = 0; np < 4; np++) {
                uint32_t bb[4];
                ldsm4(bb, kB + np * (16 * SROWB) + ks * 32);
                mma16(sC[2 * np], qua[ks], bb[0], bb[1]);
                mma16(sC[2 * np + 1], qua[ks], bb[2], bb[3]);
            }
        }

        // Online softmax; exp(S) packed straight into PV A-fragments (regs)
        uint32_t aE[4][4];
#pragma unroll
        for (int hh = 0; hh < 2; hh++) {
            int qrow = w * 16 + gid + 8 * hh;
            float sv[16];
            float mx = -1e30f;
#pragma unroll
            for (int nt = 0; nt < 8; nt++) {
#pragma unroll
                for (int cc = 0; cc < 2; cc++) {
                    int jl = nt * 8 + 2 * tig + cc;
                    float s = sC[nt][2 * hh + cc] + Cp[qrow * CST + jl];
                    sv[nt * 2 + cc] = s;
                    mx = fmaxf(mx, s);
                }
            }
            mx = fmaxf(mx, __shfl_xor_sync(0xffffffffu, mx, 1));
            mx = fmaxf(mx, __shfl_xor_sync(0xffffffffu, mx, 2));
            float mn = fmaxf(m_i[hh], mx);
            float al = __expf(m_i[hh] - mn);
            float rs = 0.f;
#pragma unroll
            for (int nt = 0; nt < 8; nt++) {
                float p0 = __expf(sv[nt * 2] - mn);
                float p1 = __expf(sv[nt * 2 + 1] - mn);
                rs += p0 + p1;
                aE[nt >> 1][((nt & 1) << 1) | hh] = pack2(p0, p1);
            }
            rs += __shfl_xor_sync(0xffffffffu, rs, 1);
            rs += __shfl_xor_sync(0xffffffffu, rs, 2);
            l_i[hh] = l_i[hh] * al + rs;
            m_i[hh] = mn;
#pragma unroll
            for (int nt = 0; nt < 8; nt++) {
                oC[nt][2 * hh] *= al;
                oC[nt][2 * hh + 1] *= al;
            }
        }

        // O += exp(S) @ V   (ldmatrix pairs on Vt)
#pragma unroll
        for (int ks = 0; ks < 4; ks++) {
#pragma unroll
            for (int np = 0; np < 4; np++) {
                uint32_t bb[4];
                ldsm4(bb, vB + np * (16 * SROWB) + ks * 32);
                mma16(oC[2 * np], aE[ks], bb[0], bb[1]);
                mma16(oC[2 * np + 1], aE[ks], bb[2], bb[3]);
            }
        }
    }

    // Write normalized output as fp16 pairs: att[b*1024+t][h*64+d]
#pragma unroll
    for (int hh = 0; hh < 2; hh++) {
        int t = i0 + w * 16 + gid + 8 * hh;
        float inv = 1.f / l_i[hh];
#pragma unroll
        for (int nt = 0; nt < 8; nt++) {
            int d = nt * 8 + 2 * tig;
            size_t i32 = (((size_t)b * 1024 + t) * 512 + h * 64 + d) >> 1;
            ((uint32_t*)att)[i32] =
                pack2(oC[nt][2 * hh] * inv, oC[nt][2 * hh + 1] * inv);
        }
    }
}

// ---------------------------------------------------------------------------
extern "C" void kernel_launch(void* const* d_in, const int* in_sizes, int n_in,
                              void* d_out, int out_size)
{
    const float* query = (const float*)d_in[0];
    const float* key   = (const float*)d_in[1];
    const float* value = (const float*)d_in[2];
    const float* pos   = (const float*)d_in[3];
    const float* Wq    = (const float*)d_in[4];
    const float* bq    = (const float*)d_in[5];
    const float* Wk    = (const float*)d_in[6];
    const float* bk    = (const float*)d_in[7];
    const float* Wv    = (const float*)d_in[8];
    const float* bv_   = (const float*)d_in[9];
    const float* Wp    = (const float*)d_in[10];
    const float* Wo    = (const float*)d_in[11];
    const float* bo    = (const float*)d_in[12];
    const float* pbu   = (const float*)d_in[13];
    const float* pbv   = (const float*)d_in[14];

    __half *qu_p, *qv_p, *k_p, *vt_p, *p_p, *att_p;
    cudaGetSymbolAddress((void**)&qu_p,  g_qu16);
    cudaGetSymbolAddress((void**)&qv_p,  g_qv16);
    cudaGetSymbolAddress((void**)&k_p,   g_k16);
    cudaGetSymbolAddress((void**)&vt_p,  g_vt16);
    cudaGetSymbolAddress((void**)&p_p,   g_p16);
    cudaGetSymbolAddress((void**)&att_p, g_att16);

    cudaFuncSetAttribute(attn_mma,
                         cudaFuncAttributeMaxDynamicSharedMemorySize,
                         ATT_SMEM_BYTES);

    gemm_fused<<<dim3(8, 64, 4), 256>>>(
        query, key, value, pos, Wq, Wk, Wv, Wp,
        bq, bk, bv_, pbu, pbv,
        qu_p, qv_p, k_p, vt_p, p_p);

    attn_mma<<<dim3(16, 64), dim3(128), ATT_SMEM_BYTES>>>(qu_p, qv_p, k_p, vt_p,
                                                          p_p, att_p);

    gemm_out<<<dim3(8, 64), 256>>>(att_p, Wo, bo, (float*)d_out);
}